// round 13
// baseline (speedup 1.0000x reference)
#include <cuda_runtime.h>
#include <cuda_bf16.h>
#include <cstdint>

#define EIN 512
#define H   96
#define BSZ 64
#define QLEN 128
#define PLEN 196

// ---------------- scratch (device globals; zero-initialized) ----------------
__device__ float g_Vt [BSZ*H*QLEN];   // [c][h][q] h-major fp32
__device__ float g_t [BSZ*H];
__device__ float g_d [BSZ*H];
__device__ float g_v [BSZ*H];

// bf16 hi/lo split operands (plain row-major [b][row][h])
__device__ __nv_bfloat16 g_Qhi[BSZ*QLEN*H];
__device__ __nv_bfloat16 g_Qlo[BSZ*QLEN*H];
__device__ __nv_bfloat16 g_Khi[BSZ*QLEN*H];
__device__ __nv_bfloat16 g_Klo[BSZ*QLEN*H];
__device__ __nv_bfloat16 g_Ahi[BSZ*QLEN*H];   // t_tok
__device__ __nv_bfloat16 g_Alo[BSZ*QLEN*H];   // (kept for layout symmetry; unused by cll now)
__device__ __nv_bfloat16 g_Bhi[BSZ*PLEN*H];   // v_patch
__device__ __nv_bfloat16 g_Blo[BSZ*PLEN*H];

// pre-converted bf16 hi/lo of all fp32 inputs + weights (15,302,656 elems)
#define CVT_TOTAL 15302656
__device__ __nv_bfloat16 g_cvthi[CVT_TOTAL];
__device__ __nv_bfloat16 g_cvtlo[CVT_TOTAL];

// ---------------- PTX helpers ----------------
__device__ __forceinline__ uint32_t smem_u32(const void* p) {
    uint32_t a;
    asm("{ .reg .u64 t; cvta.to.shared.u64 t, %1; cvt.u32.u64 %0, t; }"
        : "=r"(a) : "l"(p));
    return a;
}
__device__ __forceinline__ void ldsm_x4(uint32_t* r, uint32_t addr) {
    asm volatile("ldmatrix.sync.aligned.m8n8.x4.shared.b16 {%0,%1,%2,%3}, [%4];"
        : "=r"(r[0]),"=r"(r[1]),"=r"(r[2]),"=r"(r[3]) : "r"(addr));
}
__device__ __forceinline__ void mma16816(float* d, const uint32_t* a, const uint32_t* b) {
    asm volatile("mma.sync.aligned.m16n8k16.row.col.f32.bf16.bf16.f32 "
        "{%0,%1,%2,%3}, {%4,%5,%6,%7}, {%8,%9}, {%0,%1,%2,%3};"
        : "+f"(d[0]),"+f"(d[1]),"+f"(d[2]),"+f"(d[3])
        : "r"(a[0]),"r"(a[1]),"r"(a[2]),"r"(a[3]), "r"(b[0]),"r"(b[1]));
}
__device__ __forceinline__ uint32_t pack_hi2(float x, float y) {
    __nv_bfloat162 h = __floats2bfloat162_rn(x, y);
    return *(uint32_t*)&h;
}

// ---------------- K0: one-shot fp32 -> bf16 hi/lo conversion ----------------
struct CvtArgs {
    const float* src[14];
    void*        hi[14];
    void*        lo[14];
    int          n4[14];   // float4 count per segment
};

__global__ __launch_bounds__(256) void cvt_all(CvtArgs ca)
{
    int g = blockIdx.x*blockDim.x + threadIdx.x;
    int stride = gridDim.x*blockDim.x;
#pragma unroll 1
    for (int s=0; s<14; s++) {
        const float4* src = (const float4*)ca.src[s];
        uint2* hi = (uint2*)ca.hi[s];
        uint2* lo = (uint2*)ca.lo[s];
        int n4 = ca.n4[s];
        for (int i=g; i<n4; i+=stride) {
            float4 x = src[i];
            __nv_bfloat16 h0=__float2bfloat16(x.x), h1=__float2bfloat16(x.y),
                          h2=__float2bfloat16(x.z), h3=__float2bfloat16(x.w);
            uint2 hw, lw;
            hw.x = pack_hi2(x.x, x.y); hw.y = pack_hi2(x.z, x.w);
            lw.x = pack_hi2(x.x-__bfloat162float(h0), x.y-__bfloat162float(h1));
            lw.y = pack_hi2(x.z-__bfloat162float(h2), x.w-__bfloat162float(h3));
            hi[i] = hw; lo[i] = lw;
        }
    }
}

// ---------------- K1: batched projection via mma.sync split-bf16 (copy loader) ----------------
struct ProjArgs {
    const __nv_bfloat16 *Xh[8], *Xl[8], *Wh[8], *Wl[8];
    const float* Bv[8];
    float*       Out[8];
    void*        Out2[8];
    int          tile_start[9];
    int          l2n[8];
    int          L[8];       // >0 (mode 0): fp32 transposed [row/L][96][L]
    int          mode[8];    // 0: fp32, 1: bf16 split 128 rows/b, 2: bf16 split 196 rows/c
};

#define PRP  136                                 // padded row: 136 bf16 = 272 B
#define POFF_XHI 0
#define POFF_XLO (POFF_XHI + 64*PRP*2)
#define POFF_WHI (POFF_XLO + 64*PRP*2)
#define POFF_WLO (POFF_WHI + 96*PRP*2)
#define POFF_RED (POFF_WLO + 96*PRP*2)           // [64][2] f32 partial ss
#define SM_PROJ  (POFF_RED + 64*2*4 + 16)        // ~87.6 KB

__global__ __launch_bounds__(256,2) void proj_mma(ProjArgs pa)
{
    extern __shared__ char smem[];
    uint32_t sb = smem_u32(smem);
    int tid = threadIdx.x;
    int wid = tid >> 5, lane = tid & 31;
    int band = wid & 3, nhalf = wid >> 2;

    int bid = blockIdx.x;
    int mi = 0;
#pragma unroll
    for (int i=1;i<8;i++) if (bid >= pa.tile_start[i]) mi = i;
    int tile = bid - pa.tile_start[mi];

    const uint4* Xh4 = (const uint4*)pa.Xh[mi] + (long)tile*4096;  // 64*512/8
    const uint4* Xl4 = (const uint4*)pa.Xl[mi] + (long)tile*4096;
    const uint4* Wh4 = (const uint4*)pa.Wh[mi];
    const uint4* Wl4 = (const uint4*)pa.Wl[mi];

    float acc[6][4];
#pragma unroll
    for (int nt=0;nt<6;nt++)
#pragma unroll
        for (int i=0;i<4;i++) acc[nt][i]=0.f;

    int rrow = band*16 + (lane & 7) + ((lane >> 3) & 1) * 8;
    int rchk = ((lane >> 4) & 1) * 16;
    int brow = lane & 7;
    int bqd  = ((lane >> 3) & 3) * 16;

    for (int kc=0; kc<4; kc++) {
        __syncthreads();
        // X chunk: 64 rows x 16 uint4 (128 k) — pure copies
        for (int idx=tid; idx<64*16; idx+=256) {
            int r = idx>>4, q = idx&15;
            *(uint4*)(smem + POFF_XHI + r*(PRP*2) + q*16) = Xh4[r*64 + kc*16 + q];
            *(uint4*)(smem + POFF_XLO + r*(PRP*2) + q*16) = Xl4[r*64 + kc*16 + q];
        }
        // W chunk: 96 rows x 16 uint4
        for (int idx=tid; idx<96*16; idx+=256) {
            int r = idx>>4, q = idx&15;
            *(uint4*)(smem + POFF_WHI + r*(PRP*2) + q*16) = Wh4[r*64 + kc*16 + q];
            *(uint4*)(smem + POFF_WLO + r*(PRP*2) + q*16) = Wl4[r*64 + kc*16 + q];
        }
        __syncthreads();

#pragma unroll
        for (int ks2=0; ks2<4; ks2++) {
            uint32_t xh0[4], xh1[4], xl0[4], xl1[4];
            uint32_t abase = rrow*(PRP*2) + ks2*64 + rchk;
            ldsm_x4(xh0, sb + POFF_XHI + abase);
            ldsm_x4(xh1, sb + POFF_XHI + abase + 32);
            ldsm_x4(xl0, sb + POFF_XLO + abase);
            ldsm_x4(xl1, sb + POFF_XLO + abase + 32);
#pragma unroll
            for (int nt=0; nt<6; nt++) {
                uint32_t wh[4], wl[4];
                uint32_t bbase = (nhalf*48+nt*8+brow)*(PRP*2) + bqd + ks2*64;
                ldsm_x4(wh, sb + POFF_WHI + bbase);
                ldsm_x4(wl, sb + POFF_WLO + bbase);
                mma16816(acc[nt], xh0, wh);
                mma16816(acc[nt], xl0, wh);
                mma16816(acc[nt], xh0, wl);
                mma16816(acc[nt], xh1, wh+2);
                mma16816(acc[nt], xl1, wh+2);
                mma16816(acc[nt], xh1, wl+2);
            }
        }
    }

    int r1 = band*16 + (lane >> 2), r2 = r1 + 8;
    const float* bias = pa.Bv[mi];
#pragma unroll
    for (int nt=0; nt<6; nt++) {
        int c0 = nhalf*48 + nt*8 + (lane & 3)*2;
        float b0 = bias[c0], b1 = bias[c0+1];
        acc[nt][0] += b0; acc[nt][1] += b1;
        acc[nt][2] += b0; acc[nt][3] += b1;
    }

    if (pa.l2n[mi]) {
        float ss1 = 0.f, ss2 = 0.f;
#pragma unroll
        for (int nt=0; nt<6; nt++) {
            ss1 += acc[nt][0]*acc[nt][0] + acc[nt][1]*acc[nt][1];
            ss2 += acc[nt][2]*acc[nt][2] + acc[nt][3]*acc[nt][3];
        }
        ss1 += __shfl_xor_sync(0xffffffffu, ss1, 1);
        ss1 += __shfl_xor_sync(0xffffffffu, ss1, 2);
        ss2 += __shfl_xor_sync(0xffffffffu, ss2, 1);
        ss2 += __shfl_xor_sync(0xffffffffu, ss2, 2);
        float* red = (float*)(smem + POFF_RED);
        __syncthreads();
        if ((lane & 3) == 0) {
            red[r1*2 + nhalf] = ss1;
            red[r2*2 + nhalf] = ss2;
        }
        __syncthreads();
        float sc1 = 1.f / fmaxf(sqrtf(red[r1*2] + red[r1*2+1]), 1e-6f);
        float sc2 = 1.f / fmaxf(sqrtf(red[r2*2] + red[r2*2+1]), 1e-6f);
#pragma unroll
        for (int nt=0; nt<6; nt++) {
            acc[nt][0] *= sc1; acc[nt][1] *= sc1;
            acc[nt][2] *= sc2; acc[nt][3] *= sc2;
        }
    }

    int mode = pa.mode[mi];
    int gr1 = tile*64 + r1, gr2 = tile*64 + r2;
    if (mode) {
        int perlen = (mode==1) ? 128 : 196;
        __nv_bfloat16* hiB = (__nv_bfloat16*)pa.Out[mi];
        __nv_bfloat16* loB = (__nv_bfloat16*)pa.Out2[mi];
        int bb1 = gr1/perlen, rr1 = gr1 - bb1*perlen;
        int bb2 = gr2/perlen, rr2 = gr2 - bb2*perlen;
        long base1 = ((long)bb1*perlen + rr1)*H;
        long base2 = ((long)bb2*perlen + rr2)*H;
#pragma unroll
        for (int nt=0; nt<6; nt++) {
            int c0 = nhalf*48 + nt*8 + (lane & 3)*2;
#pragma unroll
            for (int j=0;j<2;j++) {
                float v1 = acc[nt][j], v2 = acc[nt][2+j];
                __nv_bfloat16 h1v = __float2bfloat16(v1);
                __nv_bfloat16 h2v = __float2bfloat16(v2);
                hiB[base1 + c0 + j] = h1v;
                loB[base1 + c0 + j] = __float2bfloat16(v1 - __bfloat162float(h1v));
                hiB[base2 + c0 + j] = h2v;
                loB[base2 + c0 + j] = __float2bfloat16(v2 - __bfloat162float(h2v));
            }
        }
    } else if (pa.L[mi] > 0) {
        int L = pa.L[mi];
        float* O = pa.Out[mi];
        int bb1 = gr1/L, pp1 = gr1 - bb1*L;
        int bb2 = gr2/L, pp2 = gr2 - bb2*L;
#pragma unroll
        for (int nt=0; nt<6; nt++) {
            int c0 = nhalf*48 + nt*8 + (lane & 3)*2;
#pragma unroll
            for (int j=0;j<2;j++) {
                O[((long)bb1*H + c0 + j)*L + pp1] = acc[nt][j];
                O[((long)bb2*H + c0 + j)*L + pp2] = acc[nt][2+j];
            }
        }
    } else {
        float* O = pa.Out[mi];
#pragma unroll
        for (int nt=0; nt<6; nt++) {
            int c0 = nhalf*48 + nt*8 + (lane & 3)*2;
#pragma unroll
            for (int j=0;j<2;j++) {
                O[(long)gr1*H + c0 + j] = acc[nt][j];
                O[(long)gr2*H + c0 + j] = acc[nt][2+j];
            }
        }
    }
}

// ---------------- K3: TGL via mma.sync (unchanged from R12 win) ----------------
#define TRP 104
#define TOFF_QHI 0
#define TOFF_QLO (TOFF_QHI + 128*TRP*2)
#define TOFF_KHI (TOFF_QLO + 128*TRP*2)
#define TOFF_KLO (TOFF_KHI + 128*TRP*2)
#define TOFF_CS  (TOFF_KLO + 128*TRP*2)      // [8][128] f32 colsum per band
#define TOFF_WV  (TOFF_CS + 8*128*4)         // [128] f32
#define TOFF_CTX (TOFF_WV + 128*4)           // [96] f32
#define SM_TGL   (TOFF_CTX + 96*4 + 16)      // ~111.5 KB

__global__ __launch_bounds__(256,2) void tgl_mma(
    const float* __restrict__ lng, const float* __restrict__ lnb,
    float* __restrict__ out)
{
    extern __shared__ char smem[];
    uint32_t sb = smem_u32(smem);
    int tid = threadIdx.x;
    int wid = tid >> 5, lane = tid & 31;
    int b = blockIdx.y, c = blockIdx.x;

    {
        const uint4* Qh = (const uint4*)(g_Qhi + (long)b*QLEN*H);
        const uint4* Ql = (const uint4*)(g_Qlo + (long)b*QLEN*H);
        const uint4* Kh = (const uint4*)(g_Khi + (long)c*QLEN*H);
        const uint4* Kl = (const uint4*)(g_Klo + (long)c*QLEN*H);
        uint4* dQh = (uint4*)(smem + TOFF_QHI);
        uint4* dQl = (uint4*)(smem + TOFF_QLO);
        uint4* dKh = (uint4*)(smem + TOFF_KHI);
        uint4* dKl = (uint4*)(smem + TOFF_KLO);
        for (int idx=tid; idx<128*12; idx+=256) {
            int r = idx/12, q = idx%12;
            dQh[r*13+q] = Qh[idx];
            dQl[r*13+q] = Ql[idx];
            dKh[r*13+q] = Kh[idx];
            dKl[r*13+q] = Kl[idx];
        }
    }
    __syncthreads();

    int m0 = wid*16;
    float acc[16][4];
#pragma unroll
    for (int nt=0;nt<16;nt++)
#pragma unroll
        for (int i=0;i<4;i++) acc[nt][i]=0.f;

    int rrow = m0 + (lane & 7) + ((lane >> 3) & 1) * 8;
    int rchk = ((lane >> 4) & 1) * 16;
    int brow = lane & 7;
    int bqd  = ((lane >> 3) & 3) * 16;

#pragma unroll
    for (int kc=0; kc<3; kc++) {
        uint32_t qh0[4], qh1[4], ql0[4], ql1[4];
        uint32_t abase = rrow*(TRP*2) + kc*64 + rchk;
        ldsm_x4(qh0, sb + TOFF_QHI + abase);
        ldsm_x4(qh1, sb + TOFF_QHI + abase + 32);
        ldsm_x4(ql0, sb + TOFF_QLO + abase);
        ldsm_x4(ql1, sb + TOFF_QLO + abase + 32);

        uint32_t kh[2][4], kl[2][4];
        {
            uint32_t bb0 = brow*(TRP*2) + bqd + kc*64;
            ldsm_x4(kh[0], sb + TOFF_KHI + bb0);
            ldsm_x4(kl[0], sb + TOFF_KLO + bb0);
        }
#pragma unroll
        for (int nt=0; nt<16; nt++) {
            int cur = nt & 1;
            if (nt < 15) {
                uint32_t bb = ((nt+1)*8+brow)*(TRP*2) + bqd + kc*64;
                ldsm_x4(kh[cur^1], sb + TOFF_KHI + bb);
                ldsm_x4(kl[cur^1], sb + TOFF_KLO + bb);
            }
            mma16816(acc[nt], qh0, kh[cur]);
            mma16816(acc[nt], ql0, kh[cur]);
            mma16816(acc[nt], qh0, kl[cur]);
            mma16816(acc[nt], qh1, kh[cur]+2);
            mma16816(acc[nt], ql1, kh[cur]+2);
            mma16816(acc[nt], qh1, kl[cur]+2);
        }
    }

    const float SC = 0.1020620726159658f;   // 1/sqrt(96)
    float m1 = -1e30f, m2 = -1e30f;
#pragma unroll
    for (int nt=0; nt<16; nt++) {
        m1 = fmaxf(m1, fmaxf(acc[nt][0], acc[nt][1]));
        m2 = fmaxf(m2, fmaxf(acc[nt][2], acc[nt][3]));
    }
    m1 = fmaxf(m1, __shfl_xor_sync(0xffffffffu, m1, 1));
    m1 = fmaxf(m1, __shfl_xor_sync(0xffffffffu, m1, 2));
    m2 = fmaxf(m2, __shfl_xor_sync(0xffffffffu, m2, 1));
    m2 = fmaxf(m2, __shfl_xor_sync(0xffffffffu, m2, 2));

    float s1 = 0.f, s2 = 0.f;
#pragma unroll
    for (int nt=0; nt<16; nt++) {
        float e0 = __expf((acc[nt][0]-m1)*SC);
        float e1 = __expf((acc[nt][1]-m1)*SC);
        float e2 = __expf((acc[nt][2]-m2)*SC);
        float e3 = __expf((acc[nt][3]-m2)*SC);
        acc[nt][0]=e0; acc[nt][1]=e1; acc[nt][2]=e2; acc[nt][3]=e3;
        s1 += e0+e1; s2 += e2+e3;
    }
    s1 += __shfl_xor_sync(0xffffffffu, s1, 1);
    s1 += __shfl_xor_sync(0xffffffffu, s1, 2);
    s2 += __shfl_xor_sync(0xffffffffu, s2, 1);
    s2 += __shfl_xor_sync(0xffffffffu, s2, 2);
    float inv1 = 1.f/s1, inv2 = 1.f/s2;

    float* colsum = (float*)(smem + TOFF_CS);
#pragma unroll
    for (int nt=0; nt<16; nt++) {
        float v0 = acc[nt][0]*inv1 + acc[nt][2]*inv2;
        float v1 = acc[nt][1]*inv1 + acc[nt][3]*inv2;
#pragma unroll
        for (int o=4; o<32; o<<=1) {
            v0 += __shfl_xor_sync(0xffffffffu, v0, o);
            v1 += __shfl_xor_sync(0xffffffffu, v1, o);
        }
        if (lane < 4) {
            colsum[wid*128 + nt*8 + lane*2]     = v0;
            colsum[wid*128 + nt*8 + lane*2 + 1] = v1;
        }
    }
    __syncthreads();

    float* wv = (float*)(smem + TOFF_WV);
    if (tid < 128) {
        float s = 0.f;
#pragma unroll
        for (int w=0; w<8; w++) s += colsum[w*128 + tid];
        wv[tid] = s * (1.f/128.f);
    }
    __syncthreads();

    float* ctxs = (float*)(smem + TOFF_CTX);
    if (tid < 96) {
        const float* Vr = g_Vt + (long)c*H*QLEN + tid*QLEN;
        float s = 0.f;
#pragma unroll
        for (int k4=0;k4<QLEN/4;k4++) {
            float4 v = ((const float4*)Vr)[k4];
            s += wv[k4*4]*v.x + wv[k4*4+1]*v.y + wv[k4*4+2]*v.z + wv[k4*4+3]*v.w;
        }
        ctxs[tid] = s;
    }
    __syncthreads();

    if (tid < 32) {
        float x0=ctxs[tid], x1=ctxs[tid+32], x2=ctxs[tid+64];
        float mu = x0+x1+x2;
#pragma unroll
        for (int o=16;o;o>>=1) mu += __shfl_xor_sync(0xffffffffu,mu,o);
        mu *= (1.f/96.f);
        float d0=x0-mu, d1=x1-mu, d2=x2-mu;
        float var = d0*d0 + d1*d1 + d2*d2;
#pragma unroll
        for (int o=16;o;o>>=1) var += __shfl_xor_sync(0xffffffffu,var,o);
        var *= (1.f/96.f);
        float rstd = rsqrtf(var + 1e-5f);
        float n0v = d0*rstd*lng[tid]    + lnb[tid];
        float n1v = d1*rstd*lng[tid+32] + lnb[tid+32];
        float n2v = d2*rstd*lng[tid+64] + lnb[tid+64];
        float ss = n0v*n0v + n1v*n1v + n2v*n2v;
#pragma unroll
        for (int o=16;o;o>>=1) ss += __shfl_xor_sync(0xffffffffu,ss,o);
        float sc = 1.f / fmaxf(sqrtf(ss), 1e-6f);
        const float* db = g_d + b*H;
        const float* tb = g_t + b*H;
        const float* dc = g_d + c*H;
        const float* vc = g_v + c*H;
        float part = (db[tid]*n0v + db[tid+32]*n1v + db[tid+64]*n2v)*sc
                   + tb[tid]   *(dc[tid]   +vc[tid])
                   + tb[tid+32]*(dc[tid+32]+vc[tid+32])
                   + tb[tid+64]*(dc[tid+64]+vc[tid+64]);
#pragma unroll
        for (int o=16;o;o>>=1) part += __shfl_xor_sync(0xffffffffu,part,o);
        if (tid==0) out[b*64+c] = 0.5f * part;
    }
}

// ---------------- K4: CLL via mma.sync, 2-term split (A_hi only), un-chunked B ----------------
#define RPAD 104
#define CAHI 0
#define CBHI (CAHI + 128*RPAD*2)               // 200-row B hi
#define CBLO (CBHI + 200*RPAD*2)
#define CRED (CBLO + 200*RPAD*2)
#define SM_CLL (CRED + 64)                     // ~107.3 KB

__global__ __launch_bounds__(256,2) void cll_mma(float* __restrict__ out)
{
    extern __shared__ char smem[];
    uint32_t sb = smem_u32(smem);
    int tid = threadIdx.x;
    int wid = tid >> 5, lane = tid & 31;
    int b = blockIdx.y, c = blockIdx.x;

    // load A_hi (128 rows) + full B hi/lo (196 rows + 4 zero rows)
    {
        const uint4* Ah = (const uint4*)(g_Ahi + (long)b*QLEN*H);
        const uint4* Bh = (const uint4*)(g_Bhi + (long)c*PLEN*H);
        const uint4* Bl = (const uint4*)(g_Blo + (long)c*PLEN*H);
        uint4* dAh = (uint4*)(smem + CAHI);
        uint4* dBh = (uint4*)(smem + CBHI);
        uint4* dBl = (uint4*)(smem + CBLO);
        for (int idx=tid; idx<128*12; idx+=256) {
            int r = idx/12, q = idx%12;
            dAh[r*13+q] = Ah[idx];
        }
        for (int idx=tid; idx<196*12; idx+=256) {
            int r = idx/12, q = idx%12;
            dBh[r*13+q] = Bh[idx];
            dBl[r*13+q] = Bl[idx];
        }
        uint4 z = make_uint4(0,0,0,0);
        for (int idx=tid; idx<4*12; idx+=256) {
            int r = 196 + idx/12, q = idx%12;
            dBh[r*13+q] = z;
            dBl[r*13+q] = z;
        }
    }
    __syncthreads();

    // A_hi fragments only (2-term split: D = A_hi*(B_hi + B_lo))
    int m0 = wid*16;
    uint32_t ahi[6][4];
    {
        int rrow = m0 + (lane & 7) + ((lane >> 3) & 1) * 8;
        int rchk = ((lane >> 4) & 1) * 16;
#pragma unroll
        for (int ks=0; ks<6; ks++)
            ldsm_x4(ahi[ks], sb + CAHI + rrow*(RPAD*2) + ks*32 + rchk);
    }

    float mbest = -1e30f;
    int brow = lane & 7;
    int bqd  = ((lane >> 3) & 3) * 16;

    uint32_t pbh[2][4], pbl[2][4];
    ldsm_x4(pbh[0], sb + CBHI + brow*(RPAD*2) + bqd);
    ldsm_x4(pbl[0], sb + CBLO + brow*(RPAD*2) + bqd);
#pragma unroll
    for (int nt=0; nt<25; nt++) {
        float a0[4]={0.f,0.f,0.f,0.f}, a1[4]={0.f,0.f,0.f,0.f};
#pragma unroll
        for (int ks2=0; ks2<3; ks2++) {
            int it = nt*3 + ks2;
            int cur = it & 1;
            if (it < 74) {
                int itn = it + 1;
                int ntn = itn/3, ks2n = itn - ntn*3;
                uint32_t bb = (ntn*8+brow)*(RPAD*2) + bqd + ks2n*64;
                ldsm_x4(pbh[cur^1], sb + CBHI + bb);
                ldsm_x4(pbl[cur^1], sb + CBLO + bb);
            }
            mma16816(a0, ahi[2*ks2],   pbh[cur]);
            mma16816(a1, ahi[2*ks2],   pbl[cur]);
            mma16816(a0, ahi[2*ks2+1], pbh[cur]+2);
            mma16816(a1, ahi[2*ks2+1], pbl[cur]+2);
        }
        float v0 = a0[0]+a1[0], v1 = a0[1]+a1[1];
        float v2 = a0[2]+a1[2], v3 = a0[3]+a1[3];
        if (nt < 24) {
            mbest = fmaxf(mbest, fmaxf(fmaxf(v0,v1), fmaxf(v2,v3)));
        } else {
            int col0 = nt*8 + (lane & 3)*2;
            if (col0 < PLEN)   mbest = fmaxf(mbest, fmaxf(v0, v2));
            if (col0+1 < PLEN) mbest = fmaxf(mbest, fmaxf(v1, v3));
        }
    }

#pragma unroll
    for (int o=16;o;o>>=1) mbest = fmaxf(mbest, __shfl_xor_sync(0xffffffffu,mbest,o));
    float* red = (float*)(smem + CRED);
    if (lane == 0) red[wid] = mbest;
    __syncthreads();
    if (tid == 0) {
        float m = red[0];
#pragma unroll
        for (int w=1;w<8;w++) m = fmaxf(m, red[w]);
        out[b*64+c] += 0.5f*m;
    }
}

// ---------------- host ----------------
extern "C" void kernel_launch(void* const* d_in, const int* in_sizes, int n_in,
                              void* d_out, int out_size)
{
    const float* z_d_cls = (const float*)d_in[0];
    const float* Z_d_tok = (const float*)d_in[1];
    const float* z_t_cls = (const float*)d_in[2];
    const float* Z_t_tok = (const float*)d_in[3];
    const float* z_v_cls = (const float*)d_in[4];
    const float* Z_v_pat = (const float*)d_in[5];
    const float *W_t_cls=(const float*)d_in[6],  *b_t_cls=(const float*)d_in[7];
    const float *W_d_cls=(const float*)d_in[8],  *b_d_cls=(const float*)d_in[9];
    const float *W_v_cls=(const float*)d_in[10], *b_v_cls=(const float*)d_in[11];
    const float *W_t_tok=(const float*)d_in[12], *b_t_tok=(const float*)d_in[13];
    const float *W_v_pat=(const float*)d_in[14], *b_v_pat=(const float*)d_in[15];
    const float *W_q=(const float*)d_in[16], *b_q=(const float*)d_in[17];
    const float *W_k=(const float*)d_in[18], *b_k=(const float*)d_in[19];
    const float *W_v=(const float*)d_in[20], *b_v=(const float*)d_in[21];
    const float *ln_g=(const float*)d_in[22], *ln_b=(const float*)d_in[23];
    float* out = (float*)d_out;

    float *Vp,*tp,*dp,*vp;
    void *qhi,*qlo,*khi,*klo,*ahi,*alo,*bhi,*blo;
    __nv_bfloat16 *cvh, *cvl;
    cudaGetSymbolAddress((void**)&Vp,  g_Vt);
    cudaGetSymbolAddress((void**)&tp,  g_t);
    cudaGetSymbolAddress((void**)&dp,  g_d);
    cudaGetSymbolAddress((void**)&vp,  g_v);
    cudaGetSymbolAddress(&qhi, g_Qhi);
    cudaGetSymbolAddress(&qlo, g_Qlo);
    cudaGetSymbolAddress(&khi, g_Khi);
    cudaGetSymbolAddress(&klo, g_Klo);
    cudaGetSymbolAddress(&ahi, g_Ahi);
    cudaGetSymbolAddress(&alo, g_Alo);
    cudaGetSymbolAddress(&bhi, g_Bhi);
    cudaGetSymbolAddress(&blo, g_Blo);
    cudaGetSymbolAddress((void**)&cvh, g_cvthi);
    cudaGetSymbolAddress((void**)&cvl, g_cvtlo);

    cudaFuncSetAttribute(proj_mma, cudaFuncAttributeMaxDynamicSharedMemorySize, SM_PROJ);
    cudaFuncSetAttribute(tgl_mma,  cudaFuncAttributeMaxDynamicSharedMemorySize, SM_TGL);
    cudaFuncSetAttribute(cll_mma,  cudaFuncAttributeMaxDynamicSharedMemorySize, SM_CLL);

    // ---- conversion segments: Zd, Zt, Zv, tcls, dcls, vcls, Wq,Wk,Wv,Wtt,Wvp,Wtc,Wdc,Wvc ----
    const float* srcs[14] = {Z_d_tok, Z_t_tok, Z_v_pat, z_t_cls, z_d_cls, z_v_cls,
                             W_q, W_k, W_v, W_t_tok, W_v_pat, W_t_cls, W_d_cls, W_v_cls};
    long elems[14] = {64L*128*512, 64L*128*512, 64L*196*512, 64L*512, 64L*512, 64L*512,
                      96L*512, 96L*512, 96L*512, 96L*512, 96L*512, 96L*512, 96L*512, 96L*512};
    long off[15];
    off[0] = 0;
    for (int i=0;i<14;i++) off[i+1] = off[i] + elems[i];

    CvtArgs ca;
    for (int i=0;i<14;i++) {
        ca.src[i] = srcs[i];
        ca.hi[i]  = cvh + off[i];
        ca.lo[i]  = cvl + off[i];
        ca.n4[i]  = (int)(elems[i]/4);
    }
    cvt_all<<<2048,256>>>(ca);

    // ---- projection args: per-matrix (X,W) -> pre-converted hi/lo ----
    // X segment index per matrix, W segment index per matrix:
    int xi[8] = {0, 1, 1, 1, 2, 3, 4, 5};
    int wi[8] = {6, 7, 8, 9, 10, 11, 12, 13};
    ProjArgs pa;
    for (int i=0;i<8;i++) {
        pa.Xh[i] = cvh + off[xi[i]];
        pa.Xl[i] = cvl + off[xi[i]];
        pa.Wh[i] = cvh + off[wi[i]];
        pa.Wl[i] = cvl + off[wi[i]];
        pa.Out2[i]=nullptr; pa.mode[i]=0; pa.L[i]=0; pa.l2n[i]=0;
    }
    pa.Bv[0]=b_q;     pa.Out[0]=(float*)qhi; pa.Out2[0]=qlo; pa.mode[0]=1;
    pa.Bv[1]=b_k;     pa.Out[1]=(float*)khi; pa.Out2[1]=klo; pa.mode[1]=1;
    pa.Bv[2]=b_v;     pa.Out[2]=Vp;  pa.L[2]=QLEN;
    pa.Bv[3]=b_t_tok; pa.Out[3]=(float*)ahi; pa.Out2[3]=alo; pa.l2n[3]=1; pa.mode[3]=1;
    pa.Bv[4]=b_v_pat; pa.Out[4]=(float*)bhi; pa.Out2[4]=blo; pa.l2n[4]=1; pa.mode[4]=2;
    pa.Bv[5]=b_t_cls; pa.Out[5]=tp;  pa.l2n[5]=1;
    pa.Bv[6]=b_d_cls; pa.Out[6]=dp;  pa.l2n[6]=1;
    pa.Bv[7]=b_v_cls; pa.Out[7]=vp;  pa.l2n[7]=1;
    int nt[8] = {128,128,128,128,196,1,1,1};
    pa.tile_start[0]=0;
    for (int i=0;i<8;i++) pa.tile_start[i+1]=pa.tile_start[i]+nt[i];

    proj_mma<<<pa.tile_start[8],256,SM_PROJ>>>(pa);

    // out = 0.5*(S_TGG + S_CGG + S_TGL)   (gg folded, "=" write)
    tgl_mma<<<dim3(64,64),256,SM_TGL>>>(ln_g, ln_b, out);
    // out += 0.5*S_CLL
    cll_mma<<<dim3(64,64),256,SM_CLL>>>(out);
}

// round 14
// speedup vs baseline: 1.0456x; 1.0456x over previous
#include <cuda_runtime.h>
#include <cuda_bf16.h>
#include <cstdint>

#define EIN 512
#define H   96
#define BSZ 64
#define QLEN 128
#define PLEN 196

// ---------------- scratch (device globals; zero-initialized) ----------------
__device__ float g_Vt [BSZ*H*QLEN];   // [c][h][q] h-major fp32
__device__ float g_t [BSZ*H];
__device__ float g_d [BSZ*H];
__device__ float g_v [BSZ*H];

// bf16 hi/lo split operands (plain row-major [b][row][h])
__device__ __nv_bfloat16 g_Qhi[BSZ*QLEN*H];
__device__ __nv_bfloat16 g_Qlo[BSZ*QLEN*H];
__device__ __nv_bfloat16 g_Khi[BSZ*QLEN*H];
__device__ __nv_bfloat16 g_Klo[BSZ*QLEN*H];
__device__ __nv_bfloat16 g_Ahi[BSZ*QLEN*H];   // t_tok
__device__ __nv_bfloat16 g_Alo[BSZ*QLEN*H];
__device__ __nv_bfloat16 g_Bhi[BSZ*PLEN*H];   // v_patch
__device__ __nv_bfloat16 g_Blo[BSZ*PLEN*H];

// pre-converted bf16 hi/lo of the 8 weight matrices (8 * 96 * 512)
__device__ __nv_bfloat16 g_Whi[8*96*512];
__device__ __nv_bfloat16 g_Wlo[8*96*512];

// ---------------- PTX helpers ----------------
__device__ __forceinline__ uint32_t smem_u32(const void* p) {
    uint32_t a;
    asm("{ .reg .u64 t; cvta.to.shared.u64 t, %1; cvt.u32.u64 %0, t; }"
        : "=r"(a) : "l"(p));
    return a;
}
__device__ __forceinline__ void ldsm_x4(uint32_t* r, uint32_t addr) {
    asm volatile("ldmatrix.sync.aligned.m8n8.x4.shared.b16 {%0,%1,%2,%3}, [%4];"
        : "=r"(r[0]),"=r"(r[1]),"=r"(r[2]),"=r"(r[3]) : "r"(addr));
}
__device__ __forceinline__ void mma16816(float* d, const uint32_t* a, const uint32_t* b) {
    asm volatile("mma.sync.aligned.m16n8k16.row.col.f32.bf16.bf16.f32 "
        "{%0,%1,%2,%3}, {%4,%5,%6,%7}, {%8,%9}, {%0,%1,%2,%3};"
        : "+f"(d[0]),"+f"(d[1]),"+f"(d[2]),"+f"(d[3])
        : "r"(a[0]),"r"(a[1]),"r"(a[2]),"r"(a[3]), "r"(b[0]),"r"(b[1]));
}
__device__ __forceinline__ uint32_t pack_hi2(float x, float y) {
    __nv_bfloat162 h = __floats2bfloat162_rn(x, y);
    return *(uint32_t*)&h;
}
#define CP_ASYNC16(dst, src) \
    asm volatile("cp.async.cg.shared.global [%0], [%1], 16;" \
                 :: "r"(dst), "l"(src) : "memory")
#define CP_COMMIT() asm volatile("cp.async.commit_group;" ::: "memory")
#define CP_WAIT0()  asm volatile("cp.async.wait_group 0;" ::: "memory")

// ---------------- K0: one-shot W fp32 -> bf16 hi/lo ----------------
struct CvtWArgs { const float* W[8]; };

__global__ __launch_bounds__(256) void cvt_w(CvtWArgs cw,
    __nv_bfloat16* __restrict__ whi, __nv_bfloat16* __restrict__ wlo)
{
    int mi = blockIdx.y;
    int i = blockIdx.x*blockDim.x + threadIdx.x;   // float4 index, 12288 per matrix
    const float4* src = (const float4*)cw.W[mi];
    uint2* hi = (uint2*)(whi + (long)mi*96*512);
    uint2* lo = (uint2*)(wlo + (long)mi*96*512);
    float4 x = src[i];
    __nv_bfloat16 h0=__float2bfloat16(x.x), h1=__float2bfloat16(x.y),
                  h2=__float2bfloat16(x.z), h3=__float2bfloat16(x.w);
    uint2 hw, lw;
    hw.x = pack_hi2(x.x, x.y); hw.y = pack_hi2(x.z, x.w);
    lw.x = pack_hi2(x.x-__bfloat162float(h0), x.y-__bfloat162float(h1));
    lw.y = pack_hi2(x.z-__bfloat162float(h2), x.w-__bfloat162float(h3));
    hi[i] = hw; lo[i] = lw;
}

// ---------------- K1: batched projection via mma.sync split-bf16 ----------------
struct ProjArgs {
    const float* X[8];
    const float* Bv[8];
    float*       Out[8];
    void*        Out2[8];
    int          tile_start[9];
    int          l2n[8];
    int          L[8];       // >0 (mode 0): fp32 transposed [row/L][96][L]
    int          mode[8];    // 0: fp32, 1: bf16 split 128 rows/b, 2: bf16 split 196 rows/c
};

#define PRP  136                                 // padded row: 136 bf16 = 272 B
#define POFF_XHI 0
#define POFF_XLO (POFF_XHI + 64*PRP*2)
#define POFF_WHI (POFF_XLO + 64*PRP*2)
#define POFF_WLO (POFF_WHI + 96*PRP*2)
#define POFF_RED (POFF_WLO + 96*PRP*2)           // [64][2] f32 partial ss
#define SM_PROJ  (POFF_RED + 64*2*4 + 16)        // ~87.6 KB

__global__ __launch_bounds__(256,2) void proj_mma(ProjArgs pa)
{
    extern __shared__ char smem[];
    uint32_t sb = smem_u32(smem);
    int tid = threadIdx.x;
    int wid = tid >> 5, lane = tid & 31;
    int band = wid & 3, nhalf = wid >> 2;

    int bid = blockIdx.x;
    int mi = 0;
#pragma unroll
    for (int i=1;i<8;i++) if (bid >= pa.tile_start[i]) mi = i;
    int tile = bid - pa.tile_start[mi];

    const float* Xb = pa.X[mi] + (long)tile*64*EIN;
    const uint4* Wh4 = (const uint4*)g_Whi + (long)mi*6144;   // 96*512/8
    const uint4* Wl4 = (const uint4*)g_Wlo + (long)mi*6144;

    float acc[6][4];
#pragma unroll
    for (int nt=0;nt<6;nt++)
#pragma unroll
        for (int i=0;i<4;i++) acc[nt][i]=0.f;

    int rrow = band*16 + (lane & 7) + ((lane >> 3) & 1) * 8;
    int rchk = ((lane >> 4) & 1) * 16;
    int brow = lane & 7;
    int bqd  = ((lane >> 3) & 3) * 16;

    for (int kc=0; kc<4; kc++) {
        __syncthreads();
        // X chunk: fp32 -> bf16 hi/lo fused with load
        for (int idx=tid; idx<64*32; idx+=256) {
            int r = idx>>5, k4 = idx&31;
            float4 x = *(const float4*)(Xb + r*EIN + kc*128 + k4*4);
            __nv_bfloat16 h0=__float2bfloat16(x.x), h1=__float2bfloat16(x.y),
                          h2=__float2bfloat16(x.z), h3=__float2bfloat16(x.w);
            uint2 hw, lw;
            hw.x = pack_hi2(x.x, x.y); hw.y = pack_hi2(x.z, x.w);
            lw.x = pack_hi2(x.x-__bfloat162float(h0), x.y-__bfloat162float(h1));
            lw.y = pack_hi2(x.z-__bfloat162float(h2), x.w-__bfloat162float(h3));
            *(uint2*)(smem + POFF_XHI + r*(PRP*2) + k4*8) = hw;
            *(uint2*)(smem + POFF_XLO + r*(PRP*2) + k4*8) = lw;
        }
        // W chunk: pure uint4 copies from pre-converted buffers
        for (int idx=tid; idx<96*16; idx+=256) {
            int r = idx>>4, q = idx&15;
            *(uint4*)(smem + POFF_WHI + r*(PRP*2) + q*16) = Wh4[r*64 + kc*16 + q];
            *(uint4*)(smem + POFF_WLO + r*(PRP*2) + q*16) = Wl4[r*64 + kc*16 + q];
        }
        __syncthreads();

#pragma unroll
        for (int ks2=0; ks2<4; ks2++) {
            uint32_t xh0[4], xh1[4], xl0[4], xl1[4];
            uint32_t abase = rrow*(PRP*2) + ks2*64 + rchk;
            ldsm_x4(xh0, sb + POFF_XHI + abase);
            ldsm_x4(xh1, sb + POFF_XHI + abase + 32);
            ldsm_x4(xl0, sb + POFF_XLO + abase);
            ldsm_x4(xl1, sb + POFF_XLO + abase + 32);
#pragma unroll
            for (int nt=0; nt<6; nt++) {
                uint32_t wh[4], wl[4];
                uint32_t bbase = (nhalf*48+nt*8+brow)*(PRP*2) + bqd + ks2*64;
                ldsm_x4(wh, sb + POFF_WHI + bbase);
                ldsm_x4(wl, sb + POFF_WLO + bbase);
                mma16816(acc[nt], xh0, wh);
                mma16816(acc[nt], xl0, wh);
                mma16816(acc[nt], xh0, wl);
                mma16816(acc[nt], xh1, wh+2);
                mma16816(acc[nt], xl1, wh+2);
                mma16816(acc[nt], xh1, wl+2);
            }
        }
    }

    int r1 = band*16 + (lane >> 2), r2 = r1 + 8;
    const float* bias = pa.Bv[mi];
#pragma unroll
    for (int nt=0; nt<6; nt++) {
        int c0 = nhalf*48 + nt*8 + (lane & 3)*2;
        float b0 = bias[c0], b1 = bias[c0+1];
        acc[nt][0] += b0; acc[nt][1] += b1;
        acc[nt][2] += b0; acc[nt][3] += b1;
    }

    if (pa.l2n[mi]) {
        float ss1 = 0.f, ss2 = 0.f;
#pragma unroll
        for (int nt=0; nt<6; nt++) {
            ss1 += acc[nt][0]*acc[nt][0] + acc[nt][1]*acc[nt][1];
            ss2 += acc[nt][2]*acc[nt][2] + acc[nt][3]*acc[nt][3];
        }
        ss1 += __shfl_xor_sync(0xffffffffu, ss1, 1);
        ss1 += __shfl_xor_sync(0xffffffffu, ss1, 2);
        ss2 += __shfl_xor_sync(0xffffffffu, ss2, 1);
        ss2 += __shfl_xor_sync(0xffffffffu, ss2, 2);
        float* red = (float*)(smem + POFF_RED);
        __syncthreads();
        if ((lane & 3) == 0) {
            red[r1*2 + nhalf] = ss1;
            red[r2*2 + nhalf] = ss2;
        }
        __syncthreads();
        float sc1 = 1.f / fmaxf(sqrtf(red[r1*2] + red[r1*2+1]), 1e-6f);
        float sc2 = 1.f / fmaxf(sqrtf(red[r2*2] + red[r2*2+1]), 1e-6f);
#pragma unroll
        for (int nt=0; nt<6; nt++) {
            acc[nt][0] *= sc1; acc[nt][1] *= sc1;
            acc[nt][2] *= sc2; acc[nt][3] *= sc2;
        }
    }

    int mode = pa.mode[mi];
    int gr1 = tile*64 + r1, gr2 = tile*64 + r2;
    if (mode) {
        int perlen = (mode==1) ? 128 : 196;
        __nv_bfloat16* hiB = (__nv_bfloat16*)pa.Out[mi];
        __nv_bfloat16* loB = (__nv_bfloat16*)pa.Out2[mi];
        int bb1 = gr1/perlen, rr1 = gr1 - bb1*perlen;
        int bb2 = gr2/perlen, rr2 = gr2 - bb2*perlen;
        long base1 = ((long)bb1*perlen + rr1)*H;
        long base2 = ((long)bb2*perlen + rr2)*H;
#pragma unroll
        for (int nt=0; nt<6; nt++) {
            int c0 = nhalf*48 + nt*8 + (lane & 3)*2;
#pragma unroll
            for (int j=0;j<2;j++) {
                float v1 = acc[nt][j], v2 = acc[nt][2+j];
                __nv_bfloat16 h1v = __float2bfloat16(v1);
                __nv_bfloat16 h2v = __float2bfloat16(v2);
                hiB[base1 + c0 + j] = h1v;
                loB[base1 + c0 + j] = __float2bfloat16(v1 - __bfloat162float(h1v));
                hiB[base2 + c0 + j] = h2v;
                loB[base2 + c0 + j] = __float2bfloat16(v2 - __bfloat162float(h2v));
            }
        }
    } else if (pa.L[mi] > 0) {
        int L = pa.L[mi];
        float* O = pa.Out[mi];
        int bb1 = gr1/L, pp1 = gr1 - bb1*L;
        int bb2 = gr2/L, pp2 = gr2 - bb2*L;
#pragma unroll
        for (int nt=0; nt<6; nt++) {
            int c0 = nhalf*48 + nt*8 + (lane & 3)*2;
#pragma unroll
            for (int j=0;j<2;j++) {
                O[((long)bb1*H + c0 + j)*L + pp1] = acc[nt][j];
                O[((long)bb2*H + c0 + j)*L + pp2] = acc[nt][2+j];
            }
        }
    } else {
        float* O = pa.Out[mi];
#pragma unroll
        for (int nt=0; nt<6; nt++) {
            int c0 = nhalf*48 + nt*8 + (lane & 3)*2;
#pragma unroll
            for (int j=0;j<2;j++) {
                O[(long)gr1*H + c0 + j] = acc[nt][j];
                O[(long)gr2*H + c0 + j] = acc[nt][2+j];
            }
        }
    }
}

// ---------------- K3: TGL via mma.sync (256 thr, 8 warps, prefetched B frags) ----------------
#define TRP 104
#define TOFF_QHI 0
#define TOFF_QLO (TOFF_QHI + 128*TRP*2)
#define TOFF_KHI (TOFF_QLO + 128*TRP*2)
#define TOFF_KLO (TOFF_KHI + 128*TRP*2)
#define TOFF_CS  (TOFF_KLO + 128*TRP*2)      // [8][128] f32 colsum per band
#define TOFF_WV  (TOFF_CS + 8*128*4)         // [128] f32
#define TOFF_CTX (TOFF_WV + 128*4)           // [96] f32
#define SM_TGL   (TOFF_CTX + 96*4 + 16)      // ~111.5 KB

__global__ __launch_bounds__(256,2) void tgl_mma(
    const float* __restrict__ lng, const float* __restrict__ lnb,
    float* __restrict__ out)
{
    extern __shared__ char smem[];
    uint32_t sb = smem_u32(smem);
    int tid = threadIdx.x;
    int wid = tid >> 5, lane = tid & 31;
    int b = blockIdx.y, c = blockIdx.x;

    {
        const uint4* Qh = (const uint4*)(g_Qhi + (long)b*QLEN*H);
        const uint4* Ql = (const uint4*)(g_Qlo + (long)b*QLEN*H);
        const uint4* Kh = (const uint4*)(g_Khi + (long)c*QLEN*H);
        const uint4* Kl = (const uint4*)(g_Klo + (long)c*QLEN*H);
        uint4* dQh = (uint4*)(smem + TOFF_QHI);
        uint4* dQl = (uint4*)(smem + TOFF_QLO);
        uint4* dKh = (uint4*)(smem + TOFF_KHI);
        uint4* dKl = (uint4*)(smem + TOFF_KLO);
        for (int idx=tid; idx<128*12; idx+=256) {
            int r = idx/12, q = idx%12;
            dQh[r*13+q] = Qh[idx];
            dQl[r*13+q] = Ql[idx];
            dKh[r*13+q] = Kh[idx];
            dKl[r*13+q] = Kl[idx];
        }
    }
    __syncthreads();

    int m0 = wid*16;
    float acc[16][4];
#pragma unroll
    for (int nt=0;nt<16;nt++)
#pragma unroll
        for (int i=0;i<4;i++) acc[nt][i]=0.f;

    int rrow = m0 + (lane & 7) + ((lane >> 3) & 1) * 8;
    int rchk = ((lane >> 4) & 1) * 16;
    int brow = lane & 7;
    int bqd  = ((lane >> 3) & 3) * 16;

#pragma unroll
    for (int kc=0; kc<3; kc++) {
        uint32_t qh0[4], qh1[4], ql0[4], ql1[4];
        uint32_t abase = rrow*(TRP*2) + kc*64 + rchk;
        ldsm_x4(qh0, sb + TOFF_QHI + abase);
        ldsm_x4(qh1, sb + TOFF_QHI + abase + 32);
        ldsm_x4(ql0, sb + TOFF_QLO + abase);
        ldsm_x4(ql1, sb + TOFF_QLO + abase + 32);

        uint32_t kh[2][4], kl[2][4];
        {
            uint32_t bb0 = brow*(TRP*2) + bqd + kc*64;
            ldsm_x4(kh[0], sb + TOFF_KHI + bb0);
            ldsm_x4(kl[0], sb + TOFF_KLO + bb0);
        }
#pragma unroll
        for (int nt=0; nt<16; nt++) {
            int cur = nt & 1;
            if (nt < 15) {
                uint32_t bb = ((nt+1)*8+brow)*(TRP*2) + bqd + kc*64;
                ldsm_x4(kh[cur^1], sb + TOFF_KHI + bb);
                ldsm_x4(kl[cur^1], sb + TOFF_KLO + bb);
            }
            mma16816(acc[nt], qh0, kh[cur]);
            mma16816(acc[nt], ql0, kh[cur]);
            mma16816(acc[nt], qh0, kl[cur]);
            mma16816(acc[nt], qh1, kh[cur]+2);
            mma16816(acc[nt], ql1, kh[cur]+2);
            mma16816(acc[nt], qh1, kl[cur]+2);
        }
    }

    const float SC = 0.1020620726159658f;   // 1/sqrt(96)
    float m1 = -1e30f, m2 = -1e30f;
#pragma unroll
    for (int nt=0; nt<16; nt++) {
        m1 = fmaxf(m1, fmaxf(acc[nt][0], acc[nt][1]));
        m2 = fmaxf(m2, fmaxf(acc[nt][2], acc[nt][3]));
    }
    m1 = fmaxf(m1, __shfl_xor_sync(0xffffffffu, m1, 1));
    m1 = fmaxf(m1, __shfl_xor_sync(0xffffffffu, m1, 2));
    m2 = fmaxf(m2, __shfl_xor_sync(0xffffffffu, m2, 1));
    m2 = fmaxf(m2, __shfl_xor_sync(0xffffffffu, m2, 2));

    float s1 = 0.f, s2 = 0.f;
#pragma unroll
    for (int nt=0; nt<16; nt++) {
        float e0 = __expf((acc[nt][0]-m1)*SC);
        float e1 = __expf((acc[nt][1]-m1)*SC);
        float e2 = __expf((acc[nt][2]-m2)*SC);
        float e3 = __expf((acc[nt][3]-m2)*SC);
        acc[nt][0]=e0; acc[nt][1]=e1; acc[nt][2]=e2; acc[nt][3]=e3;
        s1 += e0+e1; s2 += e2+e3;
    }
    s1 += __shfl_xor_sync(0xffffffffu, s1, 1);
    s1 += __shfl_xor_sync(0xffffffffu, s1, 2);
    s2 += __shfl_xor_sync(0xffffffffu, s2, 1);
    s2 += __shfl_xor_sync(0xffffffffu, s2, 2);
    float inv1 = 1.f/s1, inv2 = 1.f/s2;

    float* colsum = (float*)(smem + TOFF_CS);
#pragma unroll
    for (int nt=0; nt<16; nt++) {
        float v0 = acc[nt][0]*inv1 + acc[nt][2]*inv2;
        float v1 = acc[nt][1]*inv1 + acc[nt][3]*inv2;
#pragma unroll
        for (int o=4; o<32; o<<=1) {
            v0 += __shfl_xor_sync(0xffffffffu, v0, o);
            v1 += __shfl_xor_sync(0xffffffffu, v1, o);
        }
        if (lane < 4) {
            colsum[wid*128 + nt*8 + lane*2]     = v0;
            colsum[wid*128 + nt*8 + lane*2 + 1] = v1;
        }
    }
    __syncthreads();

    float* wv = (float*)(smem + TOFF_WV);
    if (tid < 128) {
        float s = 0.f;
#pragma unroll
        for (int w=0; w<8; w++) s += colsum[w*128 + tid];
        wv[tid] = s * (1.f/128.f);
    }
    __syncthreads();

    float* ctxs = (float*)(smem + TOFF_CTX);
    if (tid < 96) {
        const float* Vr = g_Vt + (long)c*H*QLEN + tid*QLEN;
        float s = 0.f;
#pragma unroll
        for (int k4=0;k4<QLEN/4;k4++) {
            float4 v = ((const float4*)Vr)[k4];
            s += wv[k4*4]*v.x + wv[k4*4+1]*v.y + wv[k4*4+2]*v.z + wv[k4*4+3]*v.w;
        }
        ctxs[tid] = s;
    }
    __syncthreads();

    if (tid < 32) {
        float x0=ctxs[tid], x1=ctxs[tid+32], x2=ctxs[tid+64];
        float mu = x0+x1+x2;
#pragma unroll
        for (int o=16;o;o>>=1) mu += __shfl_xor_sync(0xffffffffu,mu,o);
        mu *= (1.f/96.f);
        float d0=x0-mu, d1=x1-mu, d2=x2-mu;
        float var = d0*d0 + d1*d1 + d2*d2;
#pragma unroll
        for (int o=16;o;o>>=1) var += __shfl_xor_sync(0xffffffffu,var,o);
        var *= (1.f/96.f);
        float rstd = rsqrtf(var + 1e-5f);
        float n0v = d0*rstd*lng[tid]    + lnb[tid];
        float n1v = d1*rstd*lng[tid+32] + lnb[tid+32];
        float n2v = d2*rstd*lng[tid+64] + lnb[tid+64];
        float ss = n0v*n0v + n1v*n1v + n2v*n2v;
#pragma unroll
        for (int o=16;o;o>>=1) ss += __shfl_xor_sync(0xffffffffu,ss,o);
        float sc = 1.f / fmaxf(sqrtf(ss), 1e-6f);
        const float* db = g_d + b*H;
        const float* tb = g_t + b*H;
        const float* dc = g_d + c*H;
        const float* vc = g_v + c*H;
        float part = (db[tid]*n0v + db[tid+32]*n1v + db[tid+64]*n2v)*sc
                   + tb[tid]   *(dc[tid]   +vc[tid])
                   + tb[tid+32]*(dc[tid+32]+vc[tid+32])
                   + tb[tid+64]*(dc[tid+64]+vc[tid+64]);
#pragma unroll
        for (int o=16;o;o>>=1) part += __shfl_xor_sync(0xffffffffu,part,o);
        if (tid==0) out[b*64+c] = 0.5f * part;
    }
}

// ---------------- K4: CLL via mma.sync (256 thr, chunked B + cp.async overlap) ----------------
#define RPAD 104
#define COFF_AHI 0
#define COFF_ALO (COFF_AHI + 128*RPAD*2)
#define COFF_BHI (COFF_ALO + 128*RPAD*2)       // chunk0 buffer: 104 rows
#define COFF_BLO (COFF_BHI + 104*RPAD*2)
#define COFF_RED (COFF_BLO + 104*RPAD*2)
#define SM_CLL  (COFF_RED + 64)                // ~96.6 KB

__global__ __launch_bounds__(256,2) void cll_mma(float* __restrict__ out)
{
    extern __shared__ char smem[];
    uint32_t sb = smem_u32(smem);
    int tid = threadIdx.x;
    int wid = tid >> 5, lane = tid & 31;
    int b = blockIdx.y, c = blockIdx.x;

    const uint4* Bh = (const uint4*)(g_Bhi + (long)c*PLEN*H);
    const uint4* Bl = (const uint4*)(g_Blo + (long)c*PLEN*H);
    uint4* dBh = (uint4*)(smem + COFF_BHI);
    uint4* dBl = (uint4*)(smem + COFF_BLO);

    {
        const uint4* Ah = (const uint4*)(g_Ahi + (long)b*QLEN*H);
        const uint4* Al = (const uint4*)(g_Alo + (long)b*QLEN*H);
        uint4* dAh = (uint4*)(smem + COFF_AHI);
        uint4* dAl = (uint4*)(smem + COFF_ALO);
        for (int idx=tid; idx<128*12; idx+=256) {
            int r = idx/12, q = idx%12;
            dAh[r*13+q] = Ah[idx];
            dAl[r*13+q] = Al[idx];
        }
        for (int idx=tid; idx<104*12; idx+=256) {
            int r = idx/12, q = idx%12;
            dBh[r*13+q] = Bh[idx];
            dBl[r*13+q] = Bl[idx];
        }
    }
    __syncthreads();

    int m0 = wid*16;
    uint32_t ahi[6][4], alo[6][4];
    {
        int rrow = m0 + (lane & 7) + ((lane >> 3) & 1) * 8;
        int rchk = ((lane >> 4) & 1) * 16;
#pragma unroll
        for (int ks=0; ks<6; ks++) {
            ldsm_x4(ahi[ks], sb + COFF_AHI + rrow*(RPAD*2) + ks*32 + rchk);
            ldsm_x4(alo[ks], sb + COFF_ALO + rrow*(RPAD*2) + ks*32 + rchk);
        }
    }
    __syncthreads();   // all warps done reading A smem

    {
        uint4 z = make_uint4(0,0,0,0);
        for (int idx=tid; idx<4*13; idx+=256) {
            int r = 92 + idx/13, q = idx%13;
            *(uint4*)(smem + COFF_AHI + (r*13+q)*16) = z;
            *(uint4*)(smem + COFF_ALO + (r*13+q)*16) = z;
        }
        for (int idx=tid; idx<92*12; idx+=256) {
            int r = idx/12, q = idx%12;
            CP_ASYNC16(sb + COFF_AHI + (r*13+q)*16, (const void*)(Bh + (104+r)*12 + q));
            CP_ASYNC16(sb + COFF_ALO + (r*13+q)*16, (const void*)(Bl + (104+r)*12 + q));
        }
        CP_COMMIT();
    }

    float mbest = -1e30f;
    int brow = lane & 7;
    int bqd  = ((lane >> 3) & 3) * 16;

    {
        uint32_t pbh[2][4], pbl[2][4];
        ldsm_x4(pbh[0], sb + COFF_BHI + brow*(RPAD*2) + bqd);
        ldsm_x4(pbl[0], sb + COFF_BLO + brow*(RPAD*2) + bqd);
#pragma unroll
        for (int nt=0; nt<13; nt++) {
            float a0[4]={0.f,0.f,0.f,0.f}, a1[4]={0.f,0.f,0.f,0.f};
#pragma unroll
            for (int ks2=0; ks2<3; ks2++) {
                int it = nt*3 + ks2;
                int cur = it & 1;
                if (it < 38) {
                    int itn = it + 1;
                    int ntn = itn/3, ks2n = itn - ntn*3;
                    uint32_t bb = (ntn*8+brow)*(RPAD*2) + bqd + ks2n*64;
                    ldsm_x4(pbh[cur^1], sb + COFF_BHI + bb);
                    ldsm_x4(pbl[cur^1], sb + COFF_BLO + bb);
                }
                mma16816(a0, ahi[2*ks2],   pbh[cur]);
                mma16816(a1, alo[2*ks2],   pbh[cur]);
                mma16816(a0, ahi[2*ks2],   pbl[cur]);
                mma16816(a1, ahi[2*ks2+1], pbh[cur]+2);
                mma16816(a0, alo[2*ks2+1], pbh[cur]+2);
                mma16816(a1, ahi[2*ks2+1], pbl[cur]+2);
            }
            mbest = fmaxf(mbest, fmaxf(fmaxf(a0[0]+a1[0], a0[1]+a1[1]),
                                       fmaxf(a0[2]+a1[2], a0[3]+a1[3])));
        }
    }

    CP_WAIT0();
    __syncthreads();

    {
        uint32_t pbh[2][4], pbl[2][4];
        ldsm_x4(pbh[0], sb + COFF_AHI + brow*(RPAD*2) + bqd);
        ldsm_x4(pbl[0], sb + COFF_ALO + brow*(RPAD*2) + bqd);
#pragma unroll
        for (int nt=13; nt<25; nt++) {
            float a0[4]={0.f,0.f,0.f,0.f}, a1[4]={0.f,0.f,0.f,0.f};
            int lnt = nt - 13;
#pragma unroll
            for (int ks2=0; ks2<3; ks2++) {
                int it = lnt*3 + ks2;
                int cur = it & 1;
                if (it < 35) {
                    int itn = it + 1;
                    int ntn = itn/3, ks2n = itn - ntn*3;
                    uint32_t bb = (ntn*8+brow)*(RPAD*2) + bqd + ks2n*64;
                    ldsm_x4(pbh[cur^1], sb + COFF_AHI + bb);
                    ldsm_x4(pbl[cur^1], sb + COFF_ALO + bb);
                }
                mma16816(a0, ahi[2*ks2],   pbh[cur]);
                mma16816(a1, alo[2*ks2],   pbh[cur]);
                mma16816(a0, ahi[2*ks2],   pbl[cur]);
                mma16816(a1, ahi[2*ks2+1], pbh[cur]+2);
                mma16816(a0, alo[2*ks2+1], pbh[cur]+2);
                mma16816(a1, ahi[2*ks2+1], pbl[cur]+2);
            }
            int col0 = nt*8 + (lane & 3)*2;
            if (col0 < PLEN)   mbest = fmaxf(mbest, fmaxf(a0[0]+a1[0], a0[2]+a1[2]));
            if (col0+1 < PLEN) mbest = fmaxf(mbest, fmaxf(a0[1]+a1[1], a0[3]+a1[3]));
        }
    }

#pragma unroll
    for (int o=16;o;o>>=1) mbest = fmaxf(mbest, __shfl_xor_sync(0xffffffffu,mbest,o));
    float* red = (float*)(smem + COFF_RED);
    if (lane == 0) red[wid] = mbest;
    __syncthreads();
    if (tid == 0) {
        float m = red[0];
#pragma unroll
        for (int w=1;w<8;w++) m = fmaxf(m, red[w]);
        out[b*64+c] += 0.5f*m;
    }
}

// ---------------- host ----------------
extern "C" void kernel_launch(void* const* d_in, const int* in_sizes, int n_in,
                              void* d_out, int out_size)
{
    const float* z_d_cls = (const float*)d_in[0];
    const float* Z_d_tok = (const float*)d_in[1];
    const float* z_t_cls = (const float*)d_in[2];
    const float* Z_t_tok = (const float*)d_in[3];
    const float* z_v_cls = (const float*)d_in[4];
    const float* Z_v_pat = (const float*)d_in[5];
    const float *W_t_cls=(const float*)d_in[6],  *b_t_cls=(const float*)d_in[7];
    const float *W_d_cls=(const float*)d_in[8],  *b_d_cls=(const float*)d_in[9];
    const float *W_v_cls=(const float*)d_in[10], *b_v_cls=(const float*)d_in[11];
    const float *W_t_tok=(const float*)d_in[12], *b_t_tok=(const float*)d_in[13];
    const float *W_v_pat=(const float*)d_in[14], *b_v_pat=(const float*)d_in[15];
    const float *W_q=(const float*)d_in[16], *b_q=(const float*)d_in[17];
    const float *W_k=(const float*)d_in[18], *b_k=(const float*)d_in[19];
    const float *W_v=(const float*)d_in[20], *b_v=(const float*)d_in[21];
    const float *ln_g=(const float*)d_in[22], *ln_b=(const float*)d_in[23];
    float* out = (float*)d_out;

    float *Vp,*tp,*dp,*vp;
    void *qhi,*qlo,*khi,*klo,*ahi,*alo,*bhi,*blo;
    __nv_bfloat16 *whi, *wlo;
    cudaGetSymbolAddress((void**)&Vp,  g_Vt);
    cudaGetSymbolAddress((void**)&tp,  g_t);
    cudaGetSymbolAddress((void**)&dp,  g_d);
    cudaGetSymbolAddress((void**)&vp,  g_v);
    cudaGetSymbolAddress(&qhi, g_Qhi);
    cudaGetSymbolAddress(&qlo, g_Qlo);
    cudaGetSymbolAddress(&khi, g_Khi);
    cudaGetSymbolAddress(&klo, g_Klo);
    cudaGetSymbolAddress(&ahi, g_Ahi);
    cudaGetSymbolAddress(&alo, g_Alo);
    cudaGetSymbolAddress(&bhi, g_Bhi);
    cudaGetSymbolAddress(&blo, g_Blo);
    cudaGetSymbolAddress((void**)&whi, g_Whi);
    cudaGetSymbolAddress((void**)&wlo, g_Wlo);

    cudaFuncSetAttribute(proj_mma, cudaFuncAttributeMaxDynamicSharedMemorySize, SM_PROJ);
    cudaFuncSetAttribute(tgl_mma,  cudaFuncAttributeMaxDynamicSharedMemorySize, SM_TGL);
    cudaFuncSetAttribute(cll_mma,  cudaFuncAttributeMaxDynamicSharedMemorySize, SM_CLL);

    // one-shot weight conversion (matrix order matches ProjArgs mi order)
    CvtWArgs cw;
    cw.W[0]=W_q; cw.W[1]=W_k; cw.W[2]=W_v; cw.W[3]=W_t_tok;
    cw.W[4]=W_v_pat; cw.W[5]=W_t_cls; cw.W[6]=W_d_cls; cw.W[7]=W_v_cls;
    cvt_w<<<dim3(48,8),256>>>(cw, whi, wlo);

    ProjArgs pa;
    for (int i=0;i<8;i++) { pa.Out2[i]=nullptr; pa.mode[i]=0; pa.L[i]=0; pa.l2n[i]=0; }
    pa.X[0]=Z_d_tok; pa.Bv[0]=b_q;     pa.Out[0]=(float*)qhi; pa.Out2[0]=qlo; pa.mode[0]=1;
    pa.X[1]=Z_t_tok; pa.Bv[1]=b_k;     pa.Out[1]=(float*)khi; pa.Out2[1]=klo; pa.mode[1]=1;
    pa.X[2]=Z_t_tok; pa.Bv[2]=b_v;     pa.Out[2]=Vp;  pa.L[2]=QLEN;
    pa.X[3]=Z_t_tok; pa.Bv[3]=b_t_tok; pa.Out[3]=(float*)ahi; pa.Out2[3]=alo; pa.l2n[3]=1; pa.mode[3]=1;
    pa.X[4]=Z_v_pat; pa.Bv[4]=b_v_pat; pa.Out[4]=(float*)bhi; pa.Out2[4]=blo; pa.l2n[4]=1; pa.mode[4]=2;
    pa.X[5]=z_t_cls; pa.Bv[5]=b_t_cls; pa.Out[5]=tp;  pa.l2n[5]=1;
    pa.X[6]=z_d_cls; pa.Bv[6]=b_d_cls; pa.Out[6]=dp;  pa.l2n[6]=1;
    pa.X[7]=z_v_cls; pa.Bv[7]=b_v_cls; pa.Out[7]=vp;  pa.l2n[7]=1;
    int nt[8] = {128,128,128,128,196,1,1,1};
    pa.tile_start[0]=0;
    for (int i=0;i<8;i++) pa.tile_start[i+1]=pa.tile_start[i]+nt[i];

    proj_mma<<<pa.tile_start[8],256,SM_PROJ>>>(pa);

    // out = 0.5*(S_TGG + S_CGG + S_TGL)   (gg folded, "=" write)
    tgl_mma<<<dim3(64,64),256,SM_TGL>>>(ln_g, ln_b, out);
    // out += 0.5*S_CLL
    cll_mma<<<dim3(64,64),256,SM_CLL>>>(out);
}

// round 15
// speedup vs baseline: 1.0907x; 1.0431x over previous
#include <cuda_runtime.h>
#include <cuda_fp16.h>
#include <cstdint>

#define EIN 512
#define H   96
#define BSZ 64
#define QLEN 128
#define PLEN 196

// ---------------- scratch (device globals; zero-initialized) ----------------
__device__ float g_Vt [BSZ*H*QLEN];   // [c][h][q] h-major fp32
__device__ float g_t [BSZ*H];
__device__ float g_d [BSZ*H];
__device__ float g_v [BSZ*H];

// fp16 hi/lo split operands (plain row-major [b][row][h])
__device__ __half g_Qhi[BSZ*QLEN*H];
__device__ __half g_Khi[BSZ*QLEN*H];
__device__ __half g_Klo[BSZ*QLEN*H];
__device__ __half g_Ahi[BSZ*QLEN*H];   // t_tok
__device__ __half g_Bhi[BSZ*PLEN*H];   // v_patch
__device__ __half g_Blo[BSZ*PLEN*H];
__device__ __half g_sink[BSZ*QLEN*H];  // unused lo outputs (Q_lo, A_lo)

// pre-converted fp16 hi/lo of the 8 weight matrices (8 * 96 * 512)
__device__ __half g_Whi[8*96*512];
__device__ __half g_Wlo[8*96*512];

// ---------------- PTX helpers ----------------
__device__ __forceinline__ uint32_t smem_u32(const void* p) {
    uint32_t a;
    asm("{ .reg .u64 t; cvta.to.shared.u64 t, %1; cvt.u32.u64 %0, t; }"
        : "=r"(a) : "l"(p));
    return a;
}
__device__ __forceinline__ void ldsm_x4(uint32_t* r, uint32_t addr) {
    asm volatile("ldmatrix.sync.aligned.m8n8.x4.shared.b16 {%0,%1,%2,%3}, [%4];"
        : "=r"(r[0]),"=r"(r[1]),"=r"(r[2]),"=r"(r[3]) : "r"(addr));
}
__device__ __forceinline__ void mma16816(float* d, const uint32_t* a, const uint32_t* b) {
    asm volatile("mma.sync.aligned.m16n8k16.row.col.f32.f16.f16.f32 "
        "{%0,%1,%2,%3}, {%4,%5,%6,%7}, {%8,%9}, {%0,%1,%2,%3};"
        : "+f"(d[0]),"+f"(d[1]),"+f"(d[2]),"+f"(d[3])
        : "r"(a[0]),"r"(a[1]),"r"(a[2]),"r"(a[3]), "r"(b[0]),"r"(b[1]));
}
__device__ __forceinline__ uint32_t pack_h2(float x, float y) {
    __half2 h = __floats2half2_rn(x, y);
    return *(uint32_t*)&h;
}

// ---------------- K0: one-shot W fp32 -> fp16 hi/lo ----------------
struct CvtWArgs { const float* W[8]; };

__global__ __launch_bounds__(256) void cvt_w(CvtWArgs cw,
    __half* __restrict__ whi, __half* __restrict__ wlo)
{
    int mi = blockIdx.y;
    int i = blockIdx.x*blockDim.x + threadIdx.x;   // float4 index, 12288 per matrix
    const float4* src = (const float4*)cw.W[mi];
    uint2* hi = (uint2*)(whi + (long)mi*96*512);
    uint2* lo = (uint2*)(wlo + (long)mi*96*512);
    float4 x = src[i];
    __half h0=__float2half_rn(x.x), h1=__float2half_rn(x.y),
           h2=__float2half_rn(x.z), h3=__float2half_rn(x.w);
    uint2 hw, lw;
    hw.x = pack_h2(x.x, x.y); hw.y = pack_h2(x.z, x.w);
    lw.x = pack_h2(x.x-__half2float(h0), x.y-__half2float(h1));
    lw.y = pack_h2(x.z-__half2float(h2), x.w-__half2float(h3));
    hi[i] = hw; lo[i] = lw;
}

// ---------------- K1: batched projection via mma.sync split-fp16 (3-term) ----------------
struct ProjArgs {
    const float* X[8];
    const float* Bv[8];
    float*       Out[8];
    void*        Out2[8];
    int          tile_start[9];
    int          l2n[8];
    int          L[8];       // >0 (mode 0): fp32 transposed [row/L][96][L]
    int          mode[8];    // 0: fp32, 1: fp16 split 128 rows/b, 2: fp16 split 196 rows/c
};

#define PRP  136                                 // padded row: 136 fp16 = 272 B
#define POFF_XHI 0
#define POFF_XLO (POFF_XHI + 64*PRP*2)
#define POFF_WHI (POFF_XLO + 64*PRP*2)
#define POFF_WLO (POFF_WHI + 96*PRP*2)
#define POFF_RED (POFF_WLO + 96*PRP*2)           // [64][2] f32 partial ss
#define SM_PROJ  (POFF_RED + 64*2*4 + 16)        // ~87.6 KB

__global__ __launch_bounds__(256,2) void proj_mma(ProjArgs pa)
{
    extern __shared__ char smem[];
    uint32_t sb = smem_u32(smem);
    int tid = threadIdx.x;
    int wid = tid >> 5, lane = tid & 31;
    int band = wid & 3, nhalf = wid >> 2;

    int bid = blockIdx.x;
    int mi = 0;
#pragma unroll
    for (int i=1;i<8;i++) if (bid >= pa.tile_start[i]) mi = i;
    int tile = bid - pa.tile_start[mi];

    const float* Xb = pa.X[mi] + (long)tile*64*EIN;
    const uint4* Wh4 = (const uint4*)g_Whi + (long)mi*6144;   // 96*512/8
    const uint4* Wl4 = (const uint4*)g_Wlo + (long)mi*6144;

    float acc[6][4];
#pragma unroll
    for (int nt=0;nt<6;nt++)
#pragma unroll
        for (int i=0;i<4;i++) acc[nt][i]=0.f;

    int rrow = band*16 + (lane & 7) + ((lane >> 3) & 1) * 8;
    int rchk = ((lane >> 4) & 1) * 16;
    int brow = lane & 7;
    int bqd  = ((lane >> 3) & 3) * 16;

    for (int kc=0; kc<4; kc++) {
        __syncthreads();
        // X chunk: fp32 -> fp16 hi/lo fused with load
        for (int idx=tid; idx<64*32; idx+=256) {
            int r = idx>>5, k4 = idx&31;
            float4 x = *(const float4*)(Xb + r*EIN + kc*128 + k4*4);
            __half h0=__float2half_rn(x.x), h1=__float2half_rn(x.y),
                   h2=__float2half_rn(x.z), h3=__float2half_rn(x.w);
            uint2 hw, lw;
            hw.x = pack_h2(x.x, x.y); hw.y = pack_h2(x.z, x.w);
            lw.x = pack_h2(x.x-__half2float(h0), x.y-__half2float(h1));
            lw.y = pack_h2(x.z-__half2float(h2), x.w-__half2float(h3));
            *(uint2*)(smem + POFF_XHI + r*(PRP*2) + k4*8) = hw;
            *(uint2*)(smem + POFF_XLO + r*(PRP*2) + k4*8) = lw;
        }
        // W chunk: pure uint4 copies from pre-converted buffers
        for (int idx=tid; idx<96*16; idx+=256) {
            int r = idx>>4, q = idx&15;
            *(uint4*)(smem + POFF_WHI + r*(PRP*2) + q*16) = Wh4[r*64 + kc*16 + q];
            *(uint4*)(smem + POFF_WLO + r*(PRP*2) + q*16) = Wl4[r*64 + kc*16 + q];
        }
        __syncthreads();

#pragma unroll
        for (int ks2=0; ks2<4; ks2++) {
            uint32_t xh0[4], xh1[4], xl0[4], xl1[4];
            uint32_t abase = rrow*(PRP*2) + ks2*64 + rchk;
            ldsm_x4(xh0, sb + POFF_XHI + abase);
            ldsm_x4(xh1, sb + POFF_XHI + abase + 32);
            ldsm_x4(xl0, sb + POFF_XLO + abase);
            ldsm_x4(xl1, sb + POFF_XLO + abase + 32);
#pragma unroll
            for (int nt=0; nt<6; nt++) {
                uint32_t wh[4], wl[4];
                uint32_t bbase = (nhalf*48+nt*8+brow)*(PRP*2) + bqd + ks2*64;
                ldsm_x4(wh, sb + POFF_WHI + bbase);
                ldsm_x4(wl, sb + POFF_WLO + bbase);
                mma16816(acc[nt], xh0, wh);
                mma16816(acc[nt], xl0, wh);
                mma16816(acc[nt], xh0, wl);
                mma16816(acc[nt], xh1, wh+2);
                mma16816(acc[nt], xl1, wh+2);
                mma16816(acc[nt], xh1, wl+2);
            }
        }
    }

    int r1 = band*16 + (lane >> 2), r2 = r1 + 8;
    const float* bias = pa.Bv[mi];
#pragma unroll
    for (int nt=0; nt<6; nt++) {
        int c0 = nhalf*48 + nt*8 + (lane & 3)*2;
        float b0 = bias[c0], b1 = bias[c0+1];
        acc[nt][0] += b0; acc[nt][1] += b1;
        acc[nt][2] += b0; acc[nt][3] += b1;
    }

    if (pa.l2n[mi]) {
        float ss1 = 0.f, ss2 = 0.f;
#pragma unroll
        for (int nt=0; nt<6; nt++) {
            ss1 += acc[nt][0]*acc[nt][0] + acc[nt][1]*acc[nt][1];
            ss2 += acc[nt][2]*acc[nt][2] + acc[nt][3]*acc[nt][3];
        }
        ss1 += __shfl_xor_sync(0xffffffffu, ss1, 1);
        ss1 += __shfl_xor_sync(0xffffffffu, ss1, 2);
        ss2 += __shfl_xor_sync(0xffffffffu, ss2, 1);
        ss2 += __shfl_xor_sync(0xffffffffu, ss2, 2);
        float* red = (float*)(smem + POFF_RED);
        __syncthreads();
        if ((lane & 3) == 0) {
            red[r1*2 + nhalf] = ss1;
            red[r2*2 + nhalf] = ss2;
        }
        __syncthreads();
        float sc1 = 1.f / fmaxf(sqrtf(red[r1*2] + red[r1*2+1]), 1e-6f);
        float sc2 = 1.f / fmaxf(sqrtf(red[r2*2] + red[r2*2+1]), 1e-6f);
#pragma unroll
        for (int nt=0; nt<6; nt++) {
            acc[nt][0] *= sc1; acc[nt][1] *= sc1;
            acc[nt][2] *= sc2; acc[nt][3] *= sc2;
        }
    }

    int mode = pa.mode[mi];
    int gr1 = tile*64 + r1, gr2 = tile*64 + r2;
    if (mode) {
        int perlen = (mode==1) ? 128 : 196;
        __half* hiB = (__half*)pa.Out[mi];
        __half* loB = (__half*)pa.Out2[mi];
        int bb1 = gr1/perlen, rr1 = gr1 - bb1*perlen;
        int bb2 = gr2/perlen, rr2 = gr2 - bb2*perlen;
        long base1 = ((long)bb1*perlen + rr1)*H;
        long base2 = ((long)bb2*perlen + rr2)*H;
#pragma unroll
        for (int nt=0; nt<6; nt++) {
            int c0 = nhalf*48 + nt*8 + (lane & 3)*2;
#pragma unroll
            for (int j=0;j<2;j++) {
                float v1 = acc[nt][j], v2 = acc[nt][2+j];
                __half h1v = __float2half_rn(v1);
                __half h2v = __float2half_rn(v2);
                hiB[base1 + c0 + j] = h1v;
                loB[base1 + c0 + j] = __float2half_rn(v1 - __half2float(h1v));
                hiB[base2 + c0 + j] = h2v;
                loB[base2 + c0 + j] = __float2half_rn(v2 - __half2float(h2v));
            }
        }
    } else if (pa.L[mi] > 0) {
        int L = pa.L[mi];
        float* O = pa.Out[mi];
        int bb1 = gr1/L, pp1 = gr1 - bb1*L;
        int bb2 = gr2/L, pp2 = gr2 - bb2*L;
#pragma unroll
        for (int nt=0; nt<6; nt++) {
            int c0 = nhalf*48 + nt*8 + (lane & 3)*2;
#pragma unroll
            for (int j=0;j<2;j++) {
                O[((long)bb1*H + c0 + j)*L + pp1] = acc[nt][j];
                O[((long)bb2*H + c0 + j)*L + pp2] = acc[nt][2+j];
            }
        }
    } else {
        float* O = pa.Out[mi];
#pragma unroll
        for (int nt=0; nt<6; nt++) {
            int c0 = nhalf*48 + nt*8 + (lane & 3)*2;
#pragma unroll
            for (int j=0;j<2;j++) {
                O[(long)gr1*H + c0 + j] = acc[nt][j];
                O[(long)gr2*H + c0 + j] = acc[nt][2+j];
            }
        }
    }
}

// ---------------- K3: TGL via mma.sync fp16 2-term (Q_hi only), prefetched K frags ----------------
#define TRP 104
#define TOFF_QHI 0
#define TOFF_KHI (TOFF_QHI + 128*TRP*2)
#define TOFF_KLO (TOFF_KHI + 128*TRP*2)
#define TOFF_CS  (TOFF_KLO + 128*TRP*2)      // [8][128] f32 colsum per band
#define TOFF_WV  (TOFF_CS + 8*128*4)         // [128] f32
#define TOFF_CTX (TOFF_WV + 128*4)           // [96] f32
#define SM_TGL   (TOFF_CTX + 96*4 + 16)      // ~84.9 KB

__global__ __launch_bounds__(256,2) void tgl_mma(
    const float* __restrict__ lng, const float* __restrict__ lnb,
    float* __restrict__ out)
{
    extern __shared__ char smem[];
    uint32_t sb = smem_u32(smem);
    int tid = threadIdx.x;
    int wid = tid >> 5, lane = tid & 31;
    int b = blockIdx.y, c = blockIdx.x;

    {
        const uint4* Qh = (const uint4*)(g_Qhi + (long)b*QLEN*H);
        const uint4* Kh = (const uint4*)(g_Khi + (long)c*QLEN*H);
        const uint4* Kl = (const uint4*)(g_Klo + (long)c*QLEN*H);
        uint4* dQh = (uint4*)(smem + TOFF_QHI);
        uint4* dKh = (uint4*)(smem + TOFF_KHI);
        uint4* dKl = (uint4*)(smem + TOFF_KLO);
        for (int idx=tid; idx<128*12; idx+=256) {
            int r = idx/12, q = idx%12;
            dQh[r*13+q] = Qh[idx];
            dKh[r*13+q] = Kh[idx];
            dKl[r*13+q] = Kl[idx];
        }
    }
    __syncthreads();

    int m0 = wid*16;
    float acc[16][4];
#pragma unroll
    for (int nt=0;nt<16;nt++)
#pragma unroll
        for (int i=0;i<4;i++) acc[nt][i]=0.f;

    int rrow = m0 + (lane & 7) + ((lane >> 3) & 1) * 8;
    int rchk = ((lane >> 4) & 1) * 16;
    int brow = lane & 7;
    int bqd  = ((lane >> 3) & 3) * 16;

#pragma unroll
    for (int kc=0; kc<3; kc++) {
        uint32_t qh0[4], qh1[4];
        uint32_t abase = rrow*(TRP*2) + kc*64 + rchk;
        ldsm_x4(qh0, sb + TOFF_QHI + abase);
        ldsm_x4(qh1, sb + TOFF_QHI + abase + 32);

        uint32_t kh[2][4], kl[2][4];
        {
            uint32_t bb0 = brow*(TRP*2) + bqd + kc*64;
            ldsm_x4(kh[0], sb + TOFF_KHI + bb0);
            ldsm_x4(kl[0], sb + TOFF_KLO + bb0);
        }
#pragma unroll
        for (int nt=0; nt<16; nt++) {
            int cur = nt & 1;
            if (nt < 15) {
                uint32_t bb = ((nt+1)*8+brow)*(TRP*2) + bqd + kc*64;
                ldsm_x4(kh[cur^1], sb + TOFF_KHI + bb);
                ldsm_x4(kl[cur^1], sb + TOFF_KLO + bb);
            }
            mma16816(acc[nt], qh0, kh[cur]);
            mma16816(acc[nt], qh0, kl[cur]);
            mma16816(acc[nt], qh1, kh[cur]+2);
            mma16816(acc[nt], qh1, kl[cur]+2);
        }
    }

    const float SC = 0.1020620726159658f;   // 1/sqrt(96)
    float m1 = -1e30f, m2 = -1e30f;
#pragma unroll
    for (int nt=0; nt<16; nt++) {
        m1 = fmaxf(m1, fmaxf(acc[nt][0], acc[nt][1]));
        m2 = fmaxf(m2, fmaxf(acc[nt][2], acc[nt][3]));
    }
    m1 = fmaxf(m1, __shfl_xor_sync(0xffffffffu, m1, 1));
    m1 = fmaxf(m1, __shfl_xor_sync(0xffffffffu, m1, 2));
    m2 = fmaxf(m2, __shfl_xor_sync(0xffffffffu, m2, 1));
    m2 = fmaxf(m2, __shfl_xor_sync(0xffffffffu, m2, 2));

    float s1 = 0.f, s2 = 0.f;
#pragma unroll
    for (int nt=0; nt<16; nt++) {
        float e0 = __expf((acc[nt][0]-m1)*SC);
        float e1 = __expf((acc[nt][1]-m1)*SC);
        float e2 = __expf((acc[nt][2]-m2)*SC);
        float e3 = __expf((acc[nt][3]-m2)*SC);
        acc[nt][0]=e0; acc[nt][1]=e1; acc[nt][2]=e2; acc[nt][3]=e3;
        s1 += e0+e1; s2 += e2+e3;
    }
    s1 += __shfl_xor_sync(0xffffffffu, s1, 1);
    s1 += __shfl_xor_sync(0xffffffffu, s1, 2);
    s2 += __shfl_xor_sync(0xffffffffu, s2, 1);
    s2 += __shfl_xor_sync(0xffffffffu, s2, 2);
    float inv1 = 1.f/s1, inv2 = 1.f/s2;

    float* colsum = (float*)(smem + TOFF_CS);
#pragma unroll
    for (int nt=0; nt<16; nt++) {
        float v0 = acc[nt][0]*inv1 + acc[nt][2]*inv2;
        float v1 = acc[nt][1]*inv1 + acc[nt][3]*inv2;
#pragma unroll
        for (int o=4; o<32; o<<=1) {
            v0 += __shfl_xor_sync(0xffffffffu, v0, o);
            v1 += __shfl_xor_sync(0xffffffffu, v1, o);
        }
        if (lane < 4) {
            colsum[wid*128 + nt*8 + lane*2]     = v0;
            colsum[wid*128 + nt*8 + lane*2 + 1] = v1;
        }
    }
    __syncthreads();

    float* wv = (float*)(smem + TOFF_WV);
    if (tid < 128) {
        float s = 0.f;
#pragma unroll
        for (int w=0; w<8; w++) s += colsum[w*128 + tid];
        wv[tid] = s * (1.f/128.f);
    }
    __syncthreads();

    float* ctxs = (float*)(smem + TOFF_CTX);
    if (tid < 96) {
        const float* Vr = g_Vt + (long)c*H*QLEN + tid*QLEN;
        float s = 0.f;
#pragma unroll
        for (int k4=0;k4<QLEN/4;k4++) {
            float4 v = ((const float4*)Vr)[k4];
            s += wv[k4*4]*v.x + wv[k4*4+1]*v.y + wv[k4*4+2]*v.z + wv[k4*4+3]*v.w;
        }
        ctxs[tid] = s;
    }
    __syncthreads();

    if (tid < 32) {
        float x0=ctxs[tid], x1=ctxs[tid+32], x2=ctxs[tid+64];
        float mu = x0+x1+x2;
#pragma unroll
        for (int o=16;o;o>>=1) mu += __shfl_xor_sync(0xffffffffu,mu,o);
        mu *= (1.f/96.f);
        float d0=x0-mu, d1=x1-mu, d2=x2-mu;
        float var = d0*d0 + d1*d1 + d2*d2;
#pragma unroll
        for (int o=16;o;o>>=1) var += __shfl_xor_sync(0xffffffffu,var,o);
        var *= (1.f/96.f);
        float rstd = rsqrtf(var + 1e-5f);
        float n0v = d0*rstd*lng[tid]    + lnb[tid];
        float n1v = d1*rstd*lng[tid+32] + lnb[tid+32];
        float n2v = d2*rstd*lng[tid+64] + lnb[tid+64];
        float ss = n0v*n0v + n1v*n1v + n2v*n2v;
#pragma unroll
        for (int o=16;o;o>>=1) ss += __shfl_xor_sync(0xffffffffu,ss,o);
        float sc = 1.f / fmaxf(sqrtf(ss), 1e-6f);
        const float* db = g_d + b*H;
        const float* tb = g_t + b*H;
        const float* dc = g_d + c*H;
        const float* vc = g_v + c*H;
        float part = (db[tid]*n0v + db[tid+32]*n1v + db[tid+64]*n2v)*sc
                   + tb[tid]   *(dc[tid]   +vc[tid])
                   + tb[tid+32]*(dc[tid+32]+vc[tid+32])
                   + tb[tid+64]*(dc[tid+64]+vc[tid+64]);
#pragma unroll
        for (int o=16;o;o>>=1) part += __shfl_xor_sync(0xffffffffu,part,o);
        if (tid==0) out[b*64+c] = 0.5f * part;
    }
}

// ---------------- K4: CLL via mma.sync fp16 2-term (A_hi only), un-chunked B ----------------
#define RPAD 104
#define CAHI 0
#define CBHI (CAHI + 128*RPAD*2)               // 200-row B hi
#define CBLO (CBHI + 200*RPAD*2)
#define CRED (CBLO + 200*RPAD*2)
#define SM_CLL (CRED + 64)                     // ~107.3 KB

__global__ __launch_bounds__(256,2) void cll_mma(float* __restrict__ out)
{
    extern __shared__ char smem[];
    uint32_t sb = smem_u32(smem);
    int tid = threadIdx.x;
    int wid = tid >> 5, lane = tid & 31;
    int b = blockIdx.y, c = blockIdx.x;

    {
        const uint4* Ah = (const uint4*)(g_Ahi + (long)b*QLEN*H);
        const uint4* Bh = (const uint4*)(g_Bhi + (long)c*PLEN*H);
        const uint4* Bl = (const uint4*)(g_Blo + (long)c*PLEN*H);
        uint4* dAh = (uint4*)(smem + CAHI);
        uint4* dBh = (uint4*)(smem + CBHI);
        uint4* dBl = (uint4*)(smem + CBLO);
        for (int idx=tid; idx<128*12; idx+=256) {
            int r = idx/12, q = idx%12;
            dAh[r*13+q] = Ah[idx];
        }
        for (int idx=tid; idx<196*12; idx+=256) {
            int r = idx/12, q = idx%12;
            dBh[r*13+q] = Bh[idx];
            dBl[r*13+q] = Bl[idx];
        }
        uint4 z = make_uint4(0,0,0,0);
        for (int idx=tid; idx<4*12; idx+=256) {
            int r = 196 + idx/12, q = idx%12;
            dBh[r*13+q] = z;
            dBl[r*13+q] = z;
        }
    }
    __syncthreads();

    int m0 = wid*16;
    uint32_t ahi[6][4];
    {
        int rrow = m0 + (lane & 7) + ((lane >> 3) & 1) * 8;
        int rchk = ((lane >> 4) & 1) * 16;
#pragma unroll
        for (int ks=0; ks<6; ks++)
            ldsm_x4(ahi[ks], sb + CAHI + rrow*(RPAD*2) + ks*32 + rchk);
    }

    float mbest = -1e30f;
    int brow = lane & 7;
    int bqd  = ((lane >> 3) & 3) * 16;

    uint32_t pbh[2][4], pbl[2][4];
    ldsm_x4(pbh[0], sb + CBHI + brow*(RPAD*2) + bqd);
    ldsm_x4(pbl[0], sb + CBLO + brow*(RPAD*2) + bqd);
#pragma unroll
    for (int nt=0; nt<25; nt++) {
        float a0[4]={0.f,0.f,0.f,0.f}, a1[4]={0.f,0.f,0.f,0.f};
#pragma unroll
        for (int ks2=0; ks2<3; ks2++) {
            int it = nt*3 + ks2;
            int cur = it & 1;
            if (it < 74) {
                int itn = it + 1;
                int ntn = itn/3, ks2n = itn - ntn*3;
                uint32_t bb = (ntn*8+brow)*(RPAD*2) + bqd + ks2n*64;
                ldsm_x4(pbh[cur^1], sb + CBHI + bb);
                ldsm_x4(pbl[cur^1], sb + CBLO + bb);
            }
            mma16816(a0, ahi[2*ks2],   pbh[cur]);
            mma16816(a1, ahi[2*ks2],   pbl[cur]);
            mma16816(a0, ahi[2*ks2+1], pbh[cur]+2);
            mma16816(a1, ahi[2*ks2+1], pbl[cur]+2);
        }
        float v0 = a0[0]+a1[0], v1 = a0[1]+a1[1];
        float v2 = a0[2]+a1[2], v3 = a0[3]+a1[3];
        if (nt < 24) {
            mbest = fmaxf(mbest, fmaxf(fmaxf(v0,v1), fmaxf(v2,v3)));
        } else {
            int col0 = nt*8 + (lane & 3)*2;
            if (col0 < PLEN)   mbest = fmaxf(mbest, fmaxf(v0, v2));
            if (col0+1 < PLEN) mbest = fmaxf(mbest, fmaxf(v1, v3));
        }
    }

#pragma unroll
    for (int o=16;o;o>>=1) mbest = fmaxf(mbest, __shfl_xor_sync(0xffffffffu,mbest,o));
    float* red = (float*)(smem + CRED);
    if (lane == 0) red[wid] = mbest;
    __syncthreads();
    if (tid == 0) {
        float m = red[0];
#pragma unroll
        for (int w=1;w<8;w++) m = fmaxf(m, red[w]);
        out[b*64+c] += 0.5f*m;
    }
}

// ---------------- host ----------------
extern "C" void kernel_launch(void* const* d_in, const int* in_sizes, int n_in,
                              void* d_out, int out_size)
{
    const float* z_d_cls = (const float*)d_in[0];
    const float* Z_d_tok = (const float*)d_in[1];
    const float* z_t_cls = (const float*)d_in[2];
    const float* Z_t_tok = (const float*)d_in[3];
    const float* z_v_cls = (const float*)d_in[4];
    const float* Z_v_pat = (const float*)d_in[5];
    const float *W_t_cls=(const float*)d_in[6],  *b_t_cls=(const float*)d_in[7];
    const float *W_d_cls=(const float*)d_in[8],  *b_d_cls=(const float*)d_in[9];
    const float *W_v_cls=(const float*)d_in[10], *b_v_cls=(const float*)d_in[11];
    const float *W_t_tok=(const float*)d_in[12], *b_t_tok=(const float*)d_in[13];
    const float *W_v_pat=(const float*)d_in[14], *b_v_pat=(const float*)d_in[15];
    const float *W_q=(const float*)d_in[16], *b_q=(const float*)d_in[17];
    const float *W_k=(const float*)d_in[18], *b_k=(const float*)d_in[19];
    const float *W_v=(const float*)d_in[20], *b_v=(const float*)d_in[21];
    const float *ln_g=(const float*)d_in[22], *ln_b=(const float*)d_in[23];
    float* out = (float*)d_out;

    float *Vp,*tp,*dp,*vp;
    void *qhi,*khi,*klo,*ahi,*bhi,*blo,*snk;
    __half *whi, *wlo;
    cudaGetSymbolAddress((void**)&Vp,  g_Vt);
    cudaGetSymbolAddress((void**)&tp,  g_t);
    cudaGetSymbolAddress((void**)&dp,  g_d);
    cudaGetSymbolAddress((void**)&vp,  g_v);
    cudaGetSymbolAddress(&qhi, g_Qhi);
    cudaGetSymbolAddress(&khi, g_Khi);
    cudaGetSymbolAddress(&klo, g_Klo);
    cudaGetSymbolAddress(&ahi, g_Ahi);
    cudaGetSymbolAddress(&bhi, g_Bhi);
    cudaGetSymbolAddress(&blo, g_Blo);
    cudaGetSymbolAddress(&snk, g_sink);
    cudaGetSymbolAddress((void**)&whi, g_Whi);
    cudaGetSymbolAddress((void**)&wlo, g_Wlo);

    cudaFuncSetAttribute(proj_mma, cudaFuncAttributeMaxDynamicSharedMemorySize, SM_PROJ);
    cudaFuncSetAttribute(tgl_mma,  cudaFuncAttributeMaxDynamicSharedMemorySize, SM_TGL);
    cudaFuncSetAttribute(cll_mma,  cudaFuncAttributeMaxDynamicSharedMemorySize, SM_CLL);

    // one-shot weight conversion (matrix order matches ProjArgs mi order)
    CvtWArgs cw;
    cw.W[0]=W_q; cw.W[1]=W_k; cw.W[2]=W_v; cw.W[3]=W_t_tok;
    cw.W[4]=W_v_pat; cw.W[5]=W_t_cls; cw.W[6]=W_d_cls; cw.W[7]=W_v_cls;
    cvt_w<<<dim3(48,8),256>>>(cw, whi, wlo);

    ProjArgs pa;
    for (int i=0;i<8;i++) { pa.Out2[i]=nullptr; pa.mode[i]=0; pa.L[i]=0; pa.l2n[i]=0; }
    pa.X[0]=Z_d_tok; pa.Bv[0]=b_q;     pa.Out[0]=(float*)qhi; pa.Out2[0]=snk; pa.mode[0]=1;
    pa.X[1]=Z_t_tok; pa.Bv[1]=b_k;     pa.Out[1]=(float*)khi; pa.Out2[1]=klo; pa.mode[1]=1;
    pa.X[2]=Z_t_tok; pa.Bv[2]=b_v;     pa.Out[2]=Vp;  pa.L[2]=QLEN;
    pa.X[3]=Z_t_tok; pa.Bv[3]=b_t_tok; pa.Out[3]=(float*)ahi; pa.Out2[3]=snk; pa.l2n[3]=1; pa.mode[3]=1;
    pa.X[4]=Z_v_pat; pa.Bv[4]=b_v_pat; pa.Out[4]=(float*)bhi; pa.Out2[4]=blo; pa.l2n[4]=1; pa.mode[4]=2;
    pa.X[5]=z_t_cls; pa.Bv[5]=b_t_cls; pa.Out[5]=tp;  pa.l2n[5]=1;
    pa.X[6]=z_d_cls; pa.Bv[6]=b_d_cls; pa.Out[6]=dp;  pa.l2n[6]=1;
    pa.X[7]=z_v_cls; pa.Bv[7]=b_v_cls; pa.Out[7]=vp;  pa.l2n[7]=1;
    int nt[8] = {128,128,128,128,196,1,1,1};
    pa.tile_start[0]=0;
    for (int i=0;i<8;i++) pa.tile_start[i+1]=pa.tile_start[i]+nt[i];

    proj_mma<<<pa.tile_start[8],256,SM_PROJ>>>(pa);

    // out = 0.5*(S_TGG + S_CGG + S_TGL)   (gg folded, "=" write)
    tgl_mma<<<dim3(64,64),256,SM_TGL>>>(ln_g, ln_b, out);
    // out += 0.5*S_CLL
    cll_mma<<<dim3(64,64),256,SM_CLL>>>(out);
}

// round 16
// speedup vs baseline: 1.2518x; 1.1477x over previous
#include <cuda_runtime.h>
#include <cuda_fp16.h>
#include <cstdint>

#define EIN 512
#define H   96
#define BSZ 64
#define QLEN 128
#define PLEN 196

// ---------------- scratch (device globals; zero-initialized) ----------------
__device__ float g_Vt [BSZ*H*QLEN];   // [c][h][q] h-major fp32
__device__ float g_t [BSZ*H];
__device__ float g_d [BSZ*H];
__device__ float g_v [BSZ*H];

// fp16 hi/lo split operands (plain row-major [b][row][h])
__device__ __half g_Qhi[BSZ*QLEN*H];
__device__ __half g_Khi[BSZ*QLEN*H];
__device__ __half g_Klo[BSZ*QLEN*H];
__device__ __half g_Ahi[BSZ*QLEN*H];   // t_tok
__device__ __half g_Bhi[BSZ*PLEN*H];   // v_patch
__device__ __half g_Blo[BSZ*PLEN*H];
__device__ __half g_sink[BSZ*QLEN*H];  // unused lo outputs (Q_lo, A_lo)

// pre-converted fp16 hi/lo of the 8 weight matrices (8 * 96 * 512)
__device__ __half g_Whi[8*96*512];
__device__ __half g_Wlo[8*96*512];

// ---------------- PTX helpers ----------------
__device__ __forceinline__ uint32_t smem_u32(const void* p) {
    uint32_t a;
    asm("{ .reg .u64 t; cvta.to.shared.u64 t, %1; cvt.u32.u64 %0, t; }"
        : "=r"(a) : "l"(p));
    return a;
}
__device__ __forceinline__ void ldsm_x4(uint32_t* r, uint32_t addr) {
    asm volatile("ldmatrix.sync.aligned.m8n8.x4.shared.b16 {%0,%1,%2,%3}, [%4];"
        : "=r"(r[0]),"=r"(r[1]),"=r"(r[2]),"=r"(r[3]) : "r"(addr));
}
__device__ __forceinline__ void mma16816(float* d, const uint32_t* a, const uint32_t* b) {
    asm volatile("mma.sync.aligned.m16n8k16.row.col.f32.f16.f16.f32 "
        "{%0,%1,%2,%3}, {%4,%5,%6,%7}, {%8,%9}, {%0,%1,%2,%3};"
        : "+f"(d[0]),"+f"(d[1]),"+f"(d[2]),"+f"(d[3])
        : "r"(a[0]),"r"(a[1]),"r"(a[2]),"r"(a[3]), "r"(b[0]),"r"(b[1]));
}
__device__ __forceinline__ uint32_t pack_h2(float x, float y) {
    __half2 h = __floats2half2_rn(x, y);
    return *(uint32_t*)&h;
}

// ---------------- K0: one-shot W fp32 -> fp16 hi/lo ----------------
struct CvtWArgs { const float* W[8]; };

__global__ __launch_bounds__(256) void cvt_w(CvtWArgs cw,
    __half* __restrict__ whi, __half* __restrict__ wlo)
{
    int mi = blockIdx.y;
    int i = blockIdx.x*blockDim.x + threadIdx.x;
    const float4* src = (const float4*)cw.W[mi];
    uint2* hi = (uint2*)(whi + (long)mi*96*512);
    uint2* lo = (uint2*)(wlo + (long)mi*96*512);
    float4 x = src[i];
    __half h0=__float2half_rn(x.x), h1=__float2half_rn(x.y),
           h2=__float2half_rn(x.z), h3=__float2half_rn(x.w);
    uint2 hw, lw;
    hw.x = pack_h2(x.x, x.y); hw.y = pack_h2(x.z, x.w);
    lw.x = pack_h2(x.x-__half2float(h0), x.y-__half2float(h1));
    lw.y = pack_h2(x.z-__half2float(h2), x.w-__half2float(h3));
    hi[i] = hw; lo[i] = lw;
}

// ---------------- K1: batched projection via mma.sync split-fp16 (3-term) ----------------
struct ProjArgs {
    const float* X[8];
    const float* Bv[8];
    float*       Out[8];
    void*        Out2[8];
    int          tile_start[9];
    int          l2n[8];
    int          L[8];
    int          mode[8];
};

#define PRP  136
#define POFF_XHI 0
#define POFF_XLO (POFF_XHI + 64*PRP*2)
#define POFF_WHI (POFF_XLO + 64*PRP*2)
#define POFF_WLO (POFF_WHI + 96*PRP*2)
#define POFF_RED (POFF_WLO + 96*PRP*2)
#define SM_PROJ  (POFF_RED + 64*2*4 + 16)

__global__ __launch_bounds__(256,2) void proj_mma(ProjArgs pa)
{
    extern __shared__ char smem[];
    uint32_t sb = smem_u32(smem);
    int tid = threadIdx.x;
    int wid = tid >> 5, lane = tid & 31;
    int band = wid & 3, nhalf = wid >> 2;

    int bid = blockIdx.x;
    int mi = 0;
#pragma unroll
    for (int i=1;i<8;i++) if (bid >= pa.tile_start[i]) mi = i;
    int tile = bid - pa.tile_start[mi];

    const float* Xb = pa.X[mi] + (long)tile*64*EIN;
    const uint4* Wh4 = (const uint4*)g_Whi + (long)mi*6144;
    const uint4* Wl4 = (const uint4*)g_Wlo + (long)mi*6144;

    float acc[6][4];
#pragma unroll
    for (int nt=0;nt<6;nt++)
#pragma unroll
        for (int i=0;i<4;i++) acc[nt][i]=0.f;

    int rrow = band*16 + (lane & 7) + ((lane >> 3) & 1) * 8;
    int rchk = ((lane >> 4) & 1) * 16;
    int brow = lane & 7;
    int bqd  = ((lane >> 3) & 3) * 16;

    for (int kc=0; kc<4; kc++) {
        __syncthreads();
        for (int idx=tid; idx<64*32; idx+=256) {
            int r = idx>>5, k4 = idx&31;
            float4 x = *(const float4*)(Xb + r*EIN + kc*128 + k4*4);
            __half h0=__float2half_rn(x.x), h1=__float2half_rn(x.y),
                   h2=__float2half_rn(x.z), h3=__float2half_rn(x.w);
            uint2 hw, lw;
            hw.x = pack_h2(x.x, x.y); hw.y = pack_h2(x.z, x.w);
            lw.x = pack_h2(x.x-__half2float(h0), x.y-__half2float(h1));
            lw.y = pack_h2(x.z-__half2float(h2), x.w-__half2float(h3));
            *(uint2*)(smem + POFF_XHI + r*(PRP*2) + k4*8) = hw;
            *(uint2*)(smem + POFF_XLO + r*(PRP*2) + k4*8) = lw;
        }
        for (int idx=tid; idx<96*16; idx+=256) {
            int r = idx>>4, q = idx&15;
            *(uint4*)(smem + POFF_WHI + r*(PRP*2) + q*16) = Wh4[r*64 + kc*16 + q];
            *(uint4*)(smem + POFF_WLO + r*(PRP*2) + q*16) = Wl4[r*64 + kc*16 + q];
        }
        __syncthreads();

#pragma unroll
        for (int ks2=0; ks2<4; ks2++) {
            uint32_t xh0[4], xh1[4], xl0[4], xl1[4];
            uint32_t abase = rrow*(PRP*2) + ks2*64 + rchk;
            ldsm_x4(xh0, sb + POFF_XHI + abase);
            ldsm_x4(xh1, sb + POFF_XHI + abase + 32);
            ldsm_x4(xl0, sb + POFF_XLO + abase);
            ldsm_x4(xl1, sb + POFF_XLO + abase + 32);
#pragma unroll
            for (int nt=0; nt<6; nt++) {
                uint32_t wh[4], wl[4];
                uint32_t bbase = (nhalf*48+nt*8+brow)*(PRP*2) + bqd + ks2*64;
                ldsm_x4(wh, sb + POFF_WHI + bbase);
                ldsm_x4(wl, sb + POFF_WLO + bbase);
                mma16816(acc[nt], xh0, wh);
                mma16816(acc[nt], xl0, wh);
                mma16816(acc[nt], xh0, wl);
                mma16816(acc[nt], xh1, wh+2);
                mma16816(acc[nt], xl1, wh+2);
                mma16816(acc[nt], xh1, wl+2);
            }
        }
    }

    int r1 = band*16 + (lane >> 2), r2 = r1 + 8;
    const float* bias = pa.Bv[mi];
#pragma unroll
    for (int nt=0; nt<6; nt++) {
        int c0 = nhalf*48 + nt*8 + (lane & 3)*2;
        float b0 = bias[c0], b1 = bias[c0+1];
        acc[nt][0] += b0; acc[nt][1] += b1;
        acc[nt][2] += b0; acc[nt][3] += b1;
    }

    if (pa.l2n[mi]) {
        float ss1 = 0.f, ss2 = 0.f;
#pragma unroll
        for (int nt=0; nt<6; nt++) {
            ss1 += acc[nt][0]*acc[nt][0] + acc[nt][1]*acc[nt][1];
            ss2 += acc[nt][2]*acc[nt][2] + acc[nt][3]*acc[nt][3];
        }
        ss1 += __shfl_xor_sync(0xffffffffu, ss1, 1);
        ss1 += __shfl_xor_sync(0xffffffffu, ss1, 2);
        ss2 += __shfl_xor_sync(0xffffffffu, ss2, 1);
        ss2 += __shfl_xor_sync(0xffffffffu, ss2, 2);
        float* red = (float*)(smem + POFF_RED);
        __syncthreads();
        if ((lane & 3) == 0) {
            red[r1*2 + nhalf] = ss1;
            red[r2*2 + nhalf] = ss2;
        }
        __syncthreads();
        float sc1 = 1.f / fmaxf(sqrtf(red[r1*2] + red[r1*2+1]), 1e-6f);
        float sc2 = 1.f / fmaxf(sqrtf(red[r2*2] + red[r2*2+1]), 1e-6f);
#pragma unroll
        for (int nt=0; nt<6; nt++) {
            acc[nt][0] *= sc1; acc[nt][1] *= sc1;
            acc[nt][2] *= sc2; acc[nt][3] *= sc2;
        }
    }

    int mode = pa.mode[mi];
    int gr1 = tile*64 + r1, gr2 = tile*64 + r2;
    if (mode) {
        int perlen = (mode==1) ? 128 : 196;
        __half* hiB = (__half*)pa.Out[mi];
        __half* loB = (__half*)pa.Out2[mi];
        int bb1 = gr1/perlen, rr1 = gr1 - bb1*perlen;
        int bb2 = gr2/perlen, rr2 = gr2 - bb2*perlen;
        long base1 = ((long)bb1*perlen + rr1)*H;
        long base2 = ((long)bb2*perlen + rr2)*H;
#pragma unroll
        for (int nt=0; nt<6; nt++) {
            int c0 = nhalf*48 + nt*8 + (lane & 3)*2;
#pragma unroll
            for (int j=0;j<2;j++) {
                float v1 = acc[nt][j], v2 = acc[nt][2+j];
                __half h1v = __float2half_rn(v1);
                __half h2v = __float2half_rn(v2);
                hiB[base1 + c0 + j] = h1v;
                loB[base1 + c0 + j] = __float2half_rn(v1 - __half2float(h1v));
                hiB[base2 + c0 + j] = h2v;
                loB[base2 + c0 + j] = __float2half_rn(v2 - __half2float(h2v));
            }
        }
    } else if (pa.L[mi] > 0) {
        int L = pa.L[mi];
        float* O = pa.Out[mi];
        int bb1 = gr1/L, pp1 = gr1 - bb1*L;
        int bb2 = gr2/L, pp2 = gr2 - bb2*L;
#pragma unroll
        for (int nt=0; nt<6; nt++) {
            int c0 = nhalf*48 + nt*8 + (lane & 3)*2;
#pragma unroll
            for (int j=0;j<2;j++) {
                O[((long)bb1*H + c0 + j)*L + pp1] = acc[nt][j];
                O[((long)bb2*H + c0 + j)*L + pp2] = acc[nt][2+j];
            }
        }
    } else {
        float* O = pa.Out[mi];
#pragma unroll
        for (int nt=0; nt<6; nt++) {
            int c0 = nhalf*48 + nt*8 + (lane & 3)*2;
#pragma unroll
            for (int j=0;j<2;j++) {
                O[(long)gr1*H + c0 + j] = acc[nt][j];
                O[(long)gr2*H + c0 + j] = acc[nt][2+j];
            }
        }
    }
}

// ---------------- K3: TGL, fp16 2-term, m=32/half-n warps, two-pass softmax ----------------
#define TRP 104
#define TOFF_QHI 0
#define TOFF_KHI (TOFF_QHI + 128*TRP*2)
#define TOFF_KLO (TOFF_KHI + 128*TRP*2)
#define TOFF_PM  (TOFF_KLO + 128*TRP*2)      // [2][128] partial row max
#define TOFF_PS  (TOFF_PM + 2*128*4)         // [2][128] partial row sum
#define TOFF_CS  (TOFF_PS + 2*128*4)         // [4][128] colsum per band
#define TOFF_WV  (TOFF_CS + 4*128*4)         // [128]
#define TOFF_CTX (TOFF_WV + 128*4)           // [96]
#define SM_TGL   (TOFF_CTX + 96*4 + 16)      // ~85.5 KB

__global__ __launch_bounds__(256,2) void tgl_mma(
    const float* __restrict__ lng, const float* __restrict__ lnb,
    float* __restrict__ out)
{
    extern __shared__ char smem[];
    uint32_t sb = smem_u32(smem);
    int tid = threadIdx.x;
    int wid = tid >> 5, lane = tid & 31;
    int band = wid & 3, half = wid >> 2;
    int b = blockIdx.y, c = blockIdx.x;

    {
        const uint4* Qh = (const uint4*)(g_Qhi + (long)b*QLEN*H);
        const uint4* Kh = (const uint4*)(g_Khi + (long)c*QLEN*H);
        const uint4* Kl = (const uint4*)(g_Klo + (long)c*QLEN*H);
        uint4* dQh = (uint4*)(smem + TOFF_QHI);
        uint4* dKh = (uint4*)(smem + TOFF_KHI);
        uint4* dKl = (uint4*)(smem + TOFF_KLO);
        for (int idx=tid; idx<128*12; idx+=256) {
            int r = idx/12, q = idx%12;
            dQh[r*13+q] = Qh[idx];
            dKh[r*13+q] = Kh[idx];
            dKl[r*13+q] = Kl[idx];
        }
    }
    __syncthreads();

    int m0 = band*32;
    float acc[8][2][4];
#pragma unroll
    for (int nt=0;nt<8;nt++)
#pragma unroll
        for (int mt=0;mt<2;mt++)
#pragma unroll
            for (int i=0;i<4;i++) acc[nt][mt][i]=0.f;

    int rbase = m0 + (lane & 7) + ((lane >> 3) & 1) * 8;
    int rchk = ((lane >> 4) & 1) * 16;
    int brow = lane & 7;
    int bqd  = ((lane >> 3) & 3) * 16;

#pragma unroll
    for (int kc=0; kc<3; kc++) {
        uint32_t qh0[2][4], qh1[2][4];
#pragma unroll
        for (int mt=0; mt<2; mt++) {
            uint32_t abase = (rbase + mt*16)*(TRP*2) + kc*64 + rchk;
            ldsm_x4(qh0[mt], sb + TOFF_QHI + abase);
            ldsm_x4(qh1[mt], sb + TOFF_QHI + abase + 32);
        }
#pragma unroll
        for (int lnt=0; lnt<8; lnt++) {
            int gnt = half*8 + lnt;
            uint32_t kh[4], kl[4];
            uint32_t bb = (gnt*8+brow)*(TRP*2) + bqd + kc*64;
            ldsm_x4(kh, sb + TOFF_KHI + bb);
            ldsm_x4(kl, sb + TOFF_KLO + bb);
#pragma unroll
            for (int mt=0; mt<2; mt++) {
                mma16816(acc[lnt][mt], qh0[mt], kh);
                mma16816(acc[lnt][mt], qh0[mt], kl);
                mma16816(acc[lnt][mt], qh1[mt], kh+2);
                mma16816(acc[lnt][mt], qh1[mt], kl+2);
            }
        }
    }

    // two-pass softmax: lane owns rows r0, r0+8 (mt0), r0+16, r0+24 (mt1)
    const float SC = 0.1020620726159658f;   // 1/sqrt(96)
    int r0 = m0 + (lane >> 2);
    float* pm = (float*)(smem + TOFF_PM);
    float* ps = (float*)(smem + TOFF_PS);

    float mx[4] = {-1e30f,-1e30f,-1e30f,-1e30f};
#pragma unroll
    for (int lnt=0; lnt<8; lnt++) {
        mx[0] = fmaxf(mx[0], fmaxf(acc[lnt][0][0], acc[lnt][0][1]));
        mx[1] = fmaxf(mx[1], fmaxf(acc[lnt][0][2], acc[lnt][0][3]));
        mx[2] = fmaxf(mx[2], fmaxf(acc[lnt][1][0], acc[lnt][1][1]));
        mx[3] = fmaxf(mx[3], fmaxf(acc[lnt][1][2], acc[lnt][1][3]));
    }
#pragma unroll
    for (int j=0;j<4;j++) {
        mx[j] = fmaxf(mx[j], __shfl_xor_sync(0xffffffffu, mx[j], 1));
        mx[j] = fmaxf(mx[j], __shfl_xor_sync(0xffffffffu, mx[j], 2));
    }
    if ((lane & 3) == 0) {
        pm[half*128 + r0]      = mx[0];
        pm[half*128 + r0 + 8]  = mx[1];
        pm[half*128 + r0 + 16] = mx[2];
        pm[half*128 + r0 + 24] = mx[3];
    }
    __syncthreads();
    float gm[4];
    gm[0] = fmaxf(pm[r0],      pm[128 + r0]);
    gm[1] = fmaxf(pm[r0 + 8],  pm[128 + r0 + 8]);
    gm[2] = fmaxf(pm[r0 + 16], pm[128 + r0 + 16]);
    gm[3] = fmaxf(pm[r0 + 24], pm[128 + r0 + 24]);

    float sv[4] = {0.f,0.f,0.f,0.f};
#pragma unroll
    for (int lnt=0; lnt<8; lnt++) {
#pragma unroll
        for (int mt=0; mt<2; mt++) {
            float e0 = __expf((acc[lnt][mt][0]-gm[2*mt])  *SC);
            float e1 = __expf((acc[lnt][mt][1]-gm[2*mt])  *SC);
            float e2 = __expf((acc[lnt][mt][2]-gm[2*mt+1])*SC);
            float e3 = __expf((acc[lnt][mt][3]-gm[2*mt+1])*SC);
            acc[lnt][mt][0]=e0; acc[lnt][mt][1]=e1;
            acc[lnt][mt][2]=e2; acc[lnt][mt][3]=e3;
            sv[2*mt]   += e0+e1;
            sv[2*mt+1] += e2+e3;
        }
    }
#pragma unroll
    for (int j=0;j<4;j++) {
        sv[j] += __shfl_xor_sync(0xffffffffu, sv[j], 1);
        sv[j] += __shfl_xor_sync(0xffffffffu, sv[j], 2);
    }
    if ((lane & 3) == 0) {
        ps[half*128 + r0]      = sv[0];
        ps[half*128 + r0 + 8]  = sv[1];
        ps[half*128 + r0 + 16] = sv[2];
        ps[half*128 + r0 + 24] = sv[3];
    }
    __syncthreads();
    float inv[4];
    inv[0] = 1.f/(ps[r0]      + ps[128 + r0]);
    inv[1] = 1.f/(ps[r0 + 8]  + ps[128 + r0 + 8]);
    inv[2] = 1.f/(ps[r0 + 16] + ps[128 + r0 + 16]);
    inv[3] = 1.f/(ps[r0 + 24] + ps[128 + r0 + 24]);

    // column partial sums over this band's 32 rows
    float* colsum = (float*)(smem + TOFF_CS);
#pragma unroll
    for (int lnt=0; lnt<8; lnt++) {
        int gnt = half*8 + lnt;
        float v0 = acc[lnt][0][0]*inv[0] + acc[lnt][0][2]*inv[1]
                 + acc[lnt][1][0]*inv[2] + acc[lnt][1][2]*inv[3];
        float v1 = acc[lnt][0][1]*inv[0] + acc[lnt][0][3]*inv[1]
                 + acc[lnt][1][1]*inv[2] + acc[lnt][1][3]*inv[3];
#pragma unroll
        for (int o=4; o<32; o<<=1) {
            v0 += __shfl_xor_sync(0xffffffffu, v0, o);
            v1 += __shfl_xor_sync(0xffffffffu, v1, o);
        }
        if (lane < 4) {
            colsum[band*128 + gnt*8 + lane*2]     = v0;
            colsum[band*128 + gnt*8 + lane*2 + 1] = v1;
        }
    }
    __syncthreads();

    float* wv = (float*)(smem + TOFF_WV);
    if (tid < 128) {
        float s = 0.f;
#pragma unroll
        for (int w=0; w<4; w++) s += colsum[w*128 + tid];
        wv[tid] = s * (1.f/128.f);
    }
    __syncthreads();

    float* ctxs = (float*)(smem + TOFF_CTX);
    if (tid < 96) {
        const float* Vr = g_Vt + (long)c*H*QLEN + tid*QLEN;
        float s = 0.f;
#pragma unroll
        for (int k4=0;k4<QLEN/4;k4++) {
            float4 v = ((const float4*)Vr)[k4];
            s += wv[k4*4]*v.x + wv[k4*4+1]*v.y + wv[k4*4+2]*v.z + wv[k4*4+3]*v.w;
        }
        ctxs[tid] = s;
    }
    __syncthreads();

    if (tid < 32) {
        float x0=ctxs[tid], x1=ctxs[tid+32], x2=ctxs[tid+64];
        float mu = x0+x1+x2;
#pragma unroll
        for (int o=16;o;o>>=1) mu += __shfl_xor_sync(0xffffffffu,mu,o);
        mu *= (1.f/96.f);
        float d0=x0-mu, d1=x1-mu, d2=x2-mu;
        float var = d0*d0 + d1*d1 + d2*d2;
#pragma unroll
        for (int o=16;o;o>>=1) var += __shfl_xor_sync(0xffffffffu,var,o);
        var *= (1.f/96.f);
        float rstd = rsqrtf(var + 1e-5f);
        float n0v = d0*rstd*lng[tid]    + lnb[tid];
        float n1v = d1*rstd*lng[tid+32] + lnb[tid+32];
        float n2v = d2*rstd*lng[tid+64] + lnb[tid+64];
        float ss = n0v*n0v + n1v*n1v + n2v*n2v;
#pragma unroll
        for (int o=16;o;o>>=1) ss += __shfl_xor_sync(0xffffffffu,ss,o);
        float sc = 1.f / fmaxf(sqrtf(ss), 1e-6f);
        const float* db = g_d + b*H;
        const float* tb = g_t + b*H;
        const float* dc = g_d + c*H;
        const float* vc = g_v + c*H;
        float part = (db[tid]*n0v + db[tid+32]*n1v + db[tid+64]*n2v)*sc
                   + tb[tid]   *(dc[tid]   +vc[tid])
                   + tb[tid+32]*(dc[tid+32]+vc[tid+32])
                   + tb[tid+64]*(dc[tid+64]+vc[tid+64]);
#pragma unroll
        for (int o=16;o;o>>=1) part += __shfl_xor_sync(0xffffffffu,part,o);
        if (tid==0) out[b*64+c] = 0.5f * part;
    }
}

// ---------------- K4: CLL, fp16 2-term, m=32/half-n warps ----------------
#define RPAD 104
#define CAHI 0
#define CBHI (CAHI + 128*RPAD*2)
#define CBLO (CBHI + 200*RPAD*2)
#define CRED (CBLO + 200*RPAD*2)
#define SM_CLL (CRED + 64)                     // ~107.3 KB

__global__ __launch_bounds__(256,2) void cll_mma(float* __restrict__ out)
{
    extern __shared__ char smem[];
    uint32_t sb = smem_u32(smem);
    int tid = threadIdx.x;
    int wid = tid >> 5, lane = tid & 31;
    int band = wid & 3, half = wid >> 2;
    int b = blockIdx.y, c = blockIdx.x;

    {
        const uint4* Ah = (const uint4*)(g_Ahi + (long)b*QLEN*H);
        const uint4* Bh = (const uint4*)(g_Bhi + (long)c*PLEN*H);
        const uint4* Bl = (const uint4*)(g_Blo + (long)c*PLEN*H);
        uint4* dAh = (uint4*)(smem + CAHI);
        uint4* dBh = (uint4*)(smem + CBHI);
        uint4* dBl = (uint4*)(smem + CBLO);
        for (int idx=tid; idx<128*12; idx+=256) {
            int r = idx/12, q = idx%12;
            dAh[r*13+q] = Ah[idx];
        }
        for (int idx=tid; idx<196*12; idx+=256) {
            int r = idx/12, q = idx%12;
            dBh[r*13+q] = Bh[idx];
            dBl[r*13+q] = Bl[idx];
        }
        uint4 z = make_uint4(0,0,0,0);
        for (int idx=tid; idx<4*12; idx+=256) {
            int r = 196 + idx/12, q = idx%12;
            dBh[r*13+q] = z;
            dBl[r*13+q] = z;
        }
    }
    __syncthreads();

    // A_hi fragments for 32-row band (2 m-tiles)
    int m0 = band*32;
    uint32_t ahi[6][2][4];
    {
        int rbase = m0 + (lane & 7) + ((lane >> 3) & 1) * 8;
        int rchk = ((lane >> 4) & 1) * 16;
#pragma unroll
        for (int ks=0; ks<6; ks++)
#pragma unroll
            for (int mt=0; mt<2; mt++)
                ldsm_x4(ahi[ks][mt], sb + CAHI + (rbase+mt*16)*(RPAD*2) + ks*32 + rchk);
    }

    float mbest = -1e30f;
    int brow = lane & 7;
    int bqd  = ((lane >> 3) & 3) * 16;
    int nt0 = half ? 13 : 0;
    int nt1 = half ? 25 : 13;
    for (int nt=nt0; nt<nt1; nt++) {
        float aH[2][4] = {{0.f,0.f,0.f,0.f},{0.f,0.f,0.f,0.f}};
        float aL[2][4] = {{0.f,0.f,0.f,0.f},{0.f,0.f,0.f,0.f}};
#pragma unroll
        for (int ks2=0; ks2<3; ks2++) {
            uint32_t bh[4], bl[4];
            uint32_t bb = (nt*8+brow)*(RPAD*2) + bqd + ks2*64;
            ldsm_x4(bh, sb + CBHI + bb);
            ldsm_x4(bl, sb + CBLO + bb);
#pragma unroll
            for (int mt=0; mt<2; mt++) {
                mma16816(aH[mt], ahi[2*ks2][mt],   bh);
                mma16816(aL[mt], ahi[2*ks2][mt],   bl);
                mma16816(aH[mt], ahi[2*ks2+1][mt], bh+2);
                mma16816(aL[mt], ahi[2*ks2+1][mt], bl+2);
            }
        }
        if (nt < 24) {
#pragma unroll
            for (int mt=0; mt<2; mt++) {
                mbest = fmaxf(mbest, fmaxf(fmaxf(aH[mt][0]+aL[mt][0], aH[mt][1]+aL[mt][1]),
                                           fmaxf(aH[mt][2]+aL[mt][2], aH[mt][3]+aL[mt][3])));
            }
        } else {
            int col0 = nt*8 + (lane & 3)*2;
#pragma unroll
            for (int mt=0; mt<2; mt++) {
                if (col0 < PLEN)   mbest = fmaxf(mbest, fmaxf(aH[mt][0]+aL[mt][0], aH[mt][2]+aL[mt][2]));
                if (col0+1 < PLEN) mbest = fmaxf(mbest, fmaxf(aH[mt][1]+aL[mt][1], aH[mt][3]+aL[mt][3]));
            }
        }
    }

#pragma unroll
    for (int o=16;o;o>>=1) mbest = fmaxf(mbest, __shfl_xor_sync(0xffffffffu,mbest,o));
    float* red = (float*)(smem + CRED);
    if (lane == 0) red[wid] = mbest;
    __syncthreads();
    if (tid == 0) {
        float m = red[0];
#pragma unroll
        for (int w=1;w<8;w++) m = fmaxf(m, red[w]);
        out[b*64+c] += 0.5f*m;
    }
}

// ---------------- host ----------------
extern "C" void kernel_launch(void* const* d_in, const int* in_sizes, int n_in,
                              void* d_out, int out_size)
{
    const float* z_d_cls = (const float*)d_in[0];
    const float* Z_d_tok = (const float*)d_in[1];
    const float* z_t_cls = (const float*)d_in[2];
    const float* Z_t_tok = (const float*)d_in[3];
    const float* z_v_cls = (const float*)d_in[4];
    const float* Z_v_pat = (const float*)d_in[5];
    const float *W_t_cls=(const float*)d_in[6],  *b_t_cls=(const float*)d_in[7];
    const float *W_d_cls=(const float*)d_in[8],  *b_d_cls=(const float*)d_in[9];
    const float *W_v_cls=(const float*)d_in[10], *b_v_cls=(const float*)d_in[11];
    const float *W_t_tok=(const float*)d_in[12], *b_t_tok=(const float*)d_in[13];
    const float *W_v_pat=(const float*)d_in[14], *b_v_pat=(const float*)d_in[15];
    const float *W_q=(const float*)d_in[16], *b_q=(const float*)d_in[17];
    const float *W_k=(const float*)d_in[18], *b_k=(const float*)d_in[19];
    const float *W_v=(const float*)d_in[20], *b_v=(const float*)d_in[21];
    const float *ln_g=(const float*)d_in[22], *ln_b=(const float*)d_in[23];
    float* out = (float*)d_out;

    float *Vp,*tp,*dp,*vp;
    void *qhi,*khi,*klo,*ahi,*bhi,*blo,*snk;
    __half *whi, *wlo;
    cudaGetSymbolAddress((void**)&Vp,  g_Vt);
    cudaGetSymbolAddress((void**)&tp,  g_t);
    cudaGetSymbolAddress((void**)&dp,  g_d);
    cudaGetSymbolAddress((void**)&vp,  g_v);
    cudaGetSymbolAddress(&qhi, g_Qhi);
    cudaGetSymbolAddress(&khi, g_Khi);
    cudaGetSymbolAddress(&klo, g_Klo);
    cudaGetSymbolAddress(&ahi, g_Ahi);
    cudaGetSymbolAddress(&bhi, g_Bhi);
    cudaGetSymbolAddress(&blo, g_Blo);
    cudaGetSymbolAddress(&snk, g_sink);
    cudaGetSymbolAddress((void**)&whi, g_Whi);
    cudaGetSymbolAddress((void**)&wlo, g_Wlo);

    cudaFuncSetAttribute(proj_mma, cudaFuncAttributeMaxDynamicSharedMemorySize, SM_PROJ);
    cudaFuncSetAttribute(tgl_mma,  cudaFuncAttributeMaxDynamicSharedMemorySize, SM_TGL);
    cudaFuncSetAttribute(cll_mma,  cudaFuncAttributeMaxDynamicSharedMemorySize, SM_CLL);

    CvtWArgs cw;
    cw.W[0]=W_q; cw.W[1]=W_k; cw.W[2]=W_v; cw.W[3]=W_t_tok;
    cw.W[4]=W_v_pat; cw.W[5]=W_t_cls; cw.W[6]=W_d_cls; cw.W[7]=W_v_cls;
    cvt_w<<<dim3(48,8),256>>>(cw, whi, wlo);

    ProjArgs pa;
    for (int i=0;i<8;i++) { pa.Out2[i]=nullptr; pa.mode[i]=0; pa.L[i]=0; pa.l2n[i]=0; }
    pa.X[0]=Z_d_tok; pa.Bv[0]=b_q;     pa.Out[0]=(float*)qhi; pa.Out2[0]=snk; pa.mode[0]=1;
    pa.X[1]=Z_t_tok; pa.Bv[1]=b_k;     pa.Out[1]=(float*)khi; pa.Out2[1]=klo; pa.mode[1]=1;
    pa.X[2]=Z_t_tok; pa.Bv[2]=b_v;     pa.Out[2]=Vp;  pa.L[2]=QLEN;
    pa.X[3]=Z_t_tok; pa.Bv[3]=b_t_tok; pa.Out[3]=(float*)ahi; pa.Out2[3]=snk; pa.l2n[3]=1; pa.mode[3]=1;
    pa.X[4]=Z_v_pat; pa.Bv[4]=b_v_pat; pa.Out[4]=(float*)bhi; pa.Out2[4]=blo; pa.l2n[4]=1; pa.mode[4]=2;
    pa.X[5]=z_t_cls; pa.Bv[5]=b_t_cls; pa.Out[5]=tp;  pa.l2n[5]=1;
    pa.X[6]=z_d_cls; pa.Bv[6]=b_d_cls; pa.Out[6]=dp;  pa.l2n[6]=1;
    pa.X[7]=z_v_cls; pa.Bv[7]=b_v_cls; pa.Out[7]=vp;  pa.l2n[7]=1;
    int nt[8] = {128,128,128,128,196,1,1,1};
    pa.tile_start[0]=0;
    for (int i=0;i<8;i++) pa.tile_start[i+1]=pa.tile_start[i]+nt[i];

    proj_mma<<<pa.tile_start[8],256,SM_PROJ>>>(pa);

    // out = 0.5*(S_TGG + S_CGG + S_TGL)   (gg folded, "=" write)
    tgl_mma<<<dim3(64,64),256,SM_TGL>>>(ln_g, ln_b, out);
    // out += 0.5*S_CLL
    cll_mma<<<dim3(64,64),256,SM_CLL>>>(out);
}